// round 1
// baseline (speedup 1.0000x reference)
#include <cuda_runtime.h>

// Problem constants
constexpr int kB   = 64;     // batch
constexpr int kC   = 128;    // CSIZE
constexpr int kV   = 256;    // VIEW[0]*VIEW[1]
constexpr int kN   = 2000;   // N_WRD
constexpr int kE   = 32;     // EMB
constexpr int TR   = 64;     // n-rows per block
constexpr int HS   = 260;    // padded row stride (floats) for H1/H2/route

// shared memory layout (floats)
constexpr int OFF_H1  = 0;                    // 64 x 260
constexpr int OFF_H2  = OFF_H1 + 64*HS;       // 64 x 260
constexpr int OFF_WT  = OFF_H2 + 64*HS;       // 8448 scratch (fc2 tile / fce / vsT / A tile / out tile)
constexpr int OFF_H0  = OFF_WT + 8448;        // 512
constexpr int OFF_WC  = OFF_H0 + 512;         // 64 x 4
constexpr int OFF_ACT = OFF_WC + 256;         // 64
constexpr int OFF_EMB = OFF_ACT + 64;         // 64 x 33
constexpr int SM_FLOATS = OFF_EMB + 64*33;    // = 44672
constexpr int SM_BYTES  = SM_FLOATS * 4;      // 178688 B

__device__ float g_h0[kB * 512];     // relu(v @ w2c_w1 + b1)
__device__ float g_vsT[kE * kV];     // vs transposed: vsT[e][v]

// ---------------------------------------------------------------------------
// Setup kernel: blocks 0..63 compute h0 for each batch; blocks 64..71 compute
// the view-space embedding vsT (32 v's per block).
// ---------------------------------------------------------------------------
__global__ void setup_kernel(const float* __restrict__ v,
                             const float* __restrict__ w2c_w1,
                             const float* __restrict__ w2c_b1,
                             const float* __restrict__ vse_w1,
                             const float* __restrict__ vse_b1,
                             const float* __restrict__ vse_w2,
                             const float* __restrict__ vse_b2) {
    int blk = blockIdx.x;
    int t = threadIdx.x;  // 512 threads
    if (blk < kB) {
        // h0[blk][t] = relu(sum_i v[blk,i] * w2c_w1[i,t] + b1[t])
        float acc = w2c_b1[t];
#pragma unroll
        for (int i = 0; i < 7; i++) acc += v[blk * 7 + i] * w2c_w1[i * 512 + t];
        g_h0[blk * 512 + t] = fmaxf(acc, 0.f);
    } else {
        int vb = (blk - kB) * 32;  // this block handles v in [vb, vb+32)
        __shared__ float hid[32][128];
        for (int idx = t; idx < 32 * 128; idx += 512) {
            int vv = idx >> 7, h = idx & 127;
            int vg = vb + vv;
            int xi = vg >> 4, yi = vg & 15;
            float x = -1.f + (2.f / 15.f) * (float)xi;
            float y = -1.f + (2.f / 15.f) * (float)yi;
            float a = x * vse_w1[h] + y * vse_w1[128 + h] + vse_b1[h];
            hid[vv][h] = fmaxf(a, 0.f);
        }
        __syncthreads();
        for (int idx = t; idx < 32 * 32; idx += 512) {
            int e = idx >> 5, vv = idx & 31;
            float acc = vse_b2[e];
#pragma unroll 8
            for (int h = 0; h < 128; h++) acc += hid[vv][h] * vse_w2[h * kE + e];
            g_vsT[e * kV + vb + vv] = acc;
        }
    }
}

// ---------------------------------------------------------------------------
// Mega kernel: one block = (batch b, 64 consecutive word indices).
// Pipeline: wcode -> fc1 -> fc2 -> {act, emb} -> relation -> softmax*act
//           -> out[:, ntile] = view_cell[b] @ route^T   (fused, no HBM route)
// ---------------------------------------------------------------------------
__global__ __launch_bounds__(256, 1)
void mega_kernel(const float* __restrict__ view_cell,
                 const float* __restrict__ w2c_w2, const float* __restrict__ w2c_b2,
                 const float* __restrict__ fc1_w,  const float* __restrict__ fc1_b,
                 const float* __restrict__ fc2_w,  const float* __restrict__ fc2_b,
                 const float* __restrict__ fca_w,  const float* __restrict__ fca_b,
                 const float* __restrict__ fce_w,  const float* __restrict__ fce_b,
                 float* __restrict__ out) {
    extern __shared__ float sm[];
    float* H1   = sm + OFF_H1;
    float* H2   = sm + OFF_H2;
    float* WT   = sm + OFF_WT;
    float* H0s  = sm + OFF_H0;
    float* WC   = sm + OFF_WC;
    float* ACT  = sm + OFF_ACT;
    float* EMBs = sm + OFF_EMB;

    const int t    = threadIdx.x;
    const int lane = t & 31;
    const int wid  = t >> 5;         // 8 warps
    const int b    = blockIdx.y;
    const int n0   = blockIdx.x * TR;

    // load h0[b] into smem
    for (int i = t; i < 512; i += 256) H0s[i] = g_h0[b * 512 + i];
    __syncthreads();

    // ---- P1: wcode[r][j] = h0 . w2c_w2[:, (n0+r)*3+j] + b2 -----------------
    if (t < TR * 3) {
        int r = t / 3, j = t - 3 * r;
        int col = (n0 + r) * 3 + j;
        float acc = 0.f;
        if (col < 3 * kN) {
            acc = w2c_b2[col];
#pragma unroll 8
            for (int k = 0; k < 512; k++) acc += H0s[k] * w2c_w2[k * 6000 + col];
        }
        WC[r * 4 + j] = acc;
    }
    __syncthreads();

    // ---- P2: h1 = relu(wcode @ fc1_w + b1) ---------------------------------
    for (int idx = t; idx < TR * 256; idx += 256) {
        int r = idx >> 8, o = idx & 255;
        float a = fc1_b[o] + WC[r * 4 + 0] * fc1_w[o]
                           + WC[r * 4 + 1] * fc1_w[256 + o]
                           + WC[r * 4 + 2] * fc1_w[512 + o];
        H1[r * HS + o] = fmaxf(a, 0.f);
    }

    // ---- P3: h2 = relu(h1 @ fc2_w + b2)  (warp=8 rows, lane=8 outs) --------
    const int rbase = wid * 8;
    float bj[8];
#pragma unroll
    for (int j = 0; j < 8; j++) bj[j] = fc2_b[lane + 32 * j];
    float acc[8][8];
#pragma unroll
    for (int rr = 0; rr < 8; rr++)
#pragma unroll
        for (int j = 0; j < 8; j++) acc[rr][j] = bj[j];

    for (int kt = 0; kt < 256; kt += 32) {
        __syncthreads();  // WT free for next tile
        const float4* src = (const float4*)(fc2_w + kt * 256);
        float4* dst = (float4*)WT;
        for (int idx = t; idx < 2048; idx += 256) dst[idx] = src[idx];
        __syncthreads();
#pragma unroll 8
        for (int k = 0; k < 32; k++) {
            float h[8];
#pragma unroll
            for (int rr = 0; rr < 8; rr++) h[rr] = H1[(rbase + rr) * HS + kt + k];
#pragma unroll
            for (int j = 0; j < 8; j++) {
                float wv = WT[k * 256 + lane + 32 * j];
#pragma unroll
                for (int rr = 0; rr < 8; rr++) acc[rr][j] = fmaf(h[rr], wv, acc[rr][j]);
            }
        }
    }
#pragma unroll
    for (int rr = 0; rr < 8; rr++)
#pragma unroll
        for (int j = 0; j < 8; j++)
            H2[(rbase + rr) * HS + lane + 32 * j] = fmaxf(acc[rr][j], 0.f);
    __syncthreads();

    // ---- P4a: cs_emb (lane = emb dim) and activation -----------------------
    for (int idx = t; idx < 256 * kE; idx += 256) WT[idx] = fce_w[idx];
    __syncthreads();
    for (int rr = 0; rr < 8; rr++) {
        int r = rbase + rr;
        const float* h2row = H2 + r * HS;
        float ae = fce_b[lane];
#pragma unroll 8
        for (int k = 0; k < 256; k++) ae = fmaf(h2row[k], WT[k * kE + lane], ae);
        EMBs[r * 33 + lane] = ae;
        float s = 0.f;
#pragma unroll
        for (int k = lane; k < 256; k += 32) s = fmaf(h2row[k], fca_w[k], s);
#pragma unroll
        for (int off = 16; off; off >>= 1) s += __shfl_xor_sync(0xffffffffu, s, off);
        if (lane == 0) ACT[r] = 1.f / (1.f + __expf(-(s + fca_b[0])));
    }
    __syncthreads();

    // ---- P4b: relation -> softmax * act -> route (stored into H1) ----------
    for (int idx = t; idx < kE * kV; idx += 256) WT[idx] = g_vsT[idx];
    __syncthreads();
    for (int rr = 0; rr < 8; rr++) {
        int r = rbase + rr;
        float rel[8];
#pragma unroll
        for (int i = 0; i < 8; i++) rel[i] = 0.f;
#pragma unroll 4
        for (int e = 0; e < kE; e++) {
            float eb = EMBs[r * 33 + e];
#pragma unroll
            for (int i = 0; i < 8; i++)
                rel[i] = fmaf(eb, WT[e * kV + lane + 32 * i], rel[i]);
        }
        float m = rel[0];
#pragma unroll
        for (int i = 1; i < 8; i++) m = fmaxf(m, rel[i]);
#pragma unroll
        for (int off = 16; off; off >>= 1)
            m = fmaxf(m, __shfl_xor_sync(0xffffffffu, m, off));
        float s = 0.f;
#pragma unroll
        for (int i = 0; i < 8; i++) { rel[i] = __expf(rel[i] - m); s += rel[i]; }
#pragma unroll
        for (int off = 16; off; off >>= 1) s += __shfl_xor_sync(0xffffffffu, s, off);
        float scale = ACT[r] / s;
#pragma unroll
        for (int i = 0; i < 8; i++) H1[r * HS + lane + 32 * i] = rel[i] * scale;
    }
    __syncthreads();

    // ---- P5: out[b, :, n0:n0+64] = view_cell[b] @ route^T ------------------
    // warp wid owns rows r = wid*8 .. wid*8+7 (n dim); lane owns c = lane*4..+3
    float oacc[4][8];
#pragma unroll
    for (int i = 0; i < 4; i++)
#pragma unroll
        for (int j = 0; j < 8; j++) oacc[i][j] = 0.f;

    const float* A = view_cell + (size_t)b * kC * kV;
    for (int v0 = 0; v0 < kV; v0 += 32) {
        __syncthreads();
        for (int idx = t; idx < kC * 32; idx += 256) {
            int c = idx >> 5, vv = idx & 31;
            WT[vv * 132 + c] = A[c * kV + v0 + vv];
        }
        __syncthreads();
#pragma unroll 8
        for (int vv = 0; vv < 32; vv++) {
            float4 a4 = *(const float4*)&WT[vv * 132 + lane * 4];
#pragma unroll
            for (int j = 0; j < 8; j++) {
                float rv = H1[(rbase + j) * HS + v0 + vv];
                oacc[0][j] = fmaf(a4.x, rv, oacc[0][j]);
                oacc[1][j] = fmaf(a4.y, rv, oacc[1][j]);
                oacc[2][j] = fmaf(a4.z, rv, oacc[2][j]);
                oacc[3][j] = fmaf(a4.w, rv, oacc[3][j]);
            }
        }
    }

    // stage out tile in smem (r-major, padded) for coalesced global stores
    __syncthreads();
#pragma unroll
    for (int j = 0; j < 8; j++) {
        float4 v4 = make_float4(oacc[0][j], oacc[1][j], oacc[2][j], oacc[3][j]);
        *(float4*)&WT[(rbase + j) * 132 + lane * 4] = v4;
    }
    __syncthreads();
    float* outb = out + (size_t)b * kC * kN;
    for (int idx = t; idx < kC * TR; idx += 256) {
        int c = idx >> 6, rr = idx & 63;
        int n = n0 + rr;
        if (n < kN) outb[c * kN + n] = WT[rr * 132 + c];
    }
}

// ---------------------------------------------------------------------------
extern "C" void kernel_launch(void* const* d_in, const int* in_sizes, int n_in,
                              void* d_out, int out_size) {
    const float* view_cell = (const float*)d_in[0];
    const float* v         = (const float*)d_in[1];
    const float* w2c_w1    = (const float*)d_in[2];
    const float* w2c_b1    = (const float*)d_in[3];
    const float* w2c_w2    = (const float*)d_in[4];
    const float* w2c_b2    = (const float*)d_in[5];
    const float* fc1_w     = (const float*)d_in[6];
    const float* fc1_b     = (const float*)d_in[7];
    const float* fc2_w     = (const float*)d_in[8];
    const float* fc2_b     = (const float*)d_in[9];
    const float* fca_w     = (const float*)d_in[10];
    const float* fca_b     = (const float*)d_in[11];
    const float* fce_w     = (const float*)d_in[12];
    const float* fce_b     = (const float*)d_in[13];
    const float* vse_w1    = (const float*)d_in[14];
    const float* vse_b1    = (const float*)d_in[15];
    const float* vse_w2    = (const float*)d_in[16];
    const float* vse_b2    = (const float*)d_in[17];
    float* out = (float*)d_out;

    cudaFuncSetAttribute(mega_kernel, cudaFuncAttributeMaxDynamicSharedMemorySize,
                         SM_BYTES);

    setup_kernel<<<kB + 8, 512>>>(v, w2c_w1, w2c_b1, vse_w1, vse_b1, vse_w2, vse_b2);

    dim3 grid((kN + TR - 1) / TR, kB);  // (32, 64)
    mega_kernel<<<grid, 256, SM_BYTES>>>(view_cell,
                                         w2c_w2, w2c_b2,
                                         fc1_w, fc1_b,
                                         fc2_w, fc2_b,
                                         fca_w, fca_b,
                                         fce_w, fce_b,
                                         out);
}

// round 3
// speedup vs baseline: 1.5002x; 1.5002x over previous
#include <cuda_runtime.h>

// Problem constants
constexpr int kB   = 64;     // batch
constexpr int kC   = 128;    // CSIZE
constexpr int kV   = 256;    // VIEW
constexpr int kN   = 2000;   // N_WRD
constexpr int kE   = 32;     // EMB
constexpr int TR   = 64;     // n-rows per block
constexpr int HS   = 260;    // padded row stride

// shared memory layout (floats) — single H buffer reused h1 -> h2 -> route
constexpr int OFF_H   = 0;                    // 64 x 260
constexpr int OFF_WT  = OFF_H + 64 * HS;      // 8448 scratch
constexpr int OFF_WC  = OFF_WT + 8448;        // 64 x 4
constexpr int OFF_ACT = OFF_WC + 256;         // 64
constexpr int OFF_EMB = OFF_ACT + 64;         // 64 x 33
constexpr int SM_FLOATS = OFF_EMB + 64 * 33;  // 27520
constexpr int SM_BYTES  = SM_FLOATS * 4;      // 110080 B  (2 CTAs/SM fit)

__device__ float g_h0[kB * 512];      // relu(v @ w2c_w1 + b1)
__device__ float g_vsT[kE * kV];      // vs transposed
__device__ float g_wcode[kB * 6000];  // h0 @ w2c_w2 + b2

// ---------------- packed f32x2 helpers --------------------------------------
__device__ __forceinline__ unsigned long long pkdup(float v) {
    unsigned long long r;
    asm("mov.b64 %0, {%1, %1};" : "=l"(r) : "f"(v));
    return r;
}
__device__ __forceinline__ void ffma2(unsigned long long& d,
                                      unsigned long long a,
                                      unsigned long long b) {
    asm("fma.rn.f32x2 %0, %1, %2, %0;" : "+l"(d) : "l"(a), "l"(b));
}
__device__ __forceinline__ float2 unpk(unsigned long long v) {
    float2 f;
    asm("mov.b64 {%0, %1}, %2;" : "=f"(f.x), "=f"(f.y) : "l"(v));
    return f;
}

// ---------------------------------------------------------------------------
// Setup 1: h0 per batch (blocks 0..63), vsT (blocks 64..71)
// ---------------------------------------------------------------------------
__global__ void setup_kernel(const float* __restrict__ v,
                             const float* __restrict__ w2c_w1,
                             const float* __restrict__ w2c_b1,
                             const float* __restrict__ vse_w1,
                             const float* __restrict__ vse_b1,
                             const float* __restrict__ vse_w2,
                             const float* __restrict__ vse_b2) {
    int blk = blockIdx.x;
    int t = threadIdx.x;  // 512
    if (blk < kB) {
        float acc = w2c_b1[t];
#pragma unroll
        for (int i = 0; i < 7; i++) acc += v[blk * 7 + i] * w2c_w1[i * 512 + t];
        g_h0[blk * 512 + t] = fmaxf(acc, 0.f);
    } else {
        int vb = (blk - kB) * 32;
        __shared__ float hid[32][128];
        for (int idx = t; idx < 32 * 128; idx += 512) {
            int vv = idx >> 7, h = idx & 127;
            int vg = vb + vv;
            int xi = vg >> 4, yi = vg & 15;
            float x = -1.f + (2.f / 15.f) * (float)xi;
            float y = -1.f + (2.f / 15.f) * (float)yi;
            float a = x * vse_w1[h] + y * vse_w1[128 + h] + vse_b1[h];
            hid[vv][h] = fmaxf(a, 0.f);
        }
        __syncthreads();
        for (int idx = t; idx < 32 * 32; idx += 512) {
            int e = idx >> 5, vv = idx & 31;
            float acc = vse_b2[e];
#pragma unroll 8
            for (int h = 0; h < 128; h++) acc += hid[vv][h] * vse_w2[h * kE + e];
            g_vsT[e * kV + vb + vv] = acc;
        }
    }
}

// ---------------------------------------------------------------------------
// Setup 2: wcode[b][col] = h0[b] . w2c_w2[:,col] + b2.
// Block = 128 cols, loops over ALL 64 batches so w2c_w2 is read exactly once.
// ---------------------------------------------------------------------------
__global__ __launch_bounds__(128)
void wcode_kernel(const float* __restrict__ w2c_w2,
                  const float* __restrict__ w2c_b2) {
    __shared__ float h0s[64 * 65];  // [k-in-tile][b], padded
    int t = threadIdx.x;
    int col = blockIdx.x * 128 + t;
    bool ok = col < 6000;
    float bias = ok ? w2c_b2[col] : 0.f;

    float acc[64];
#pragma unroll
    for (int b = 0; b < 64; b++) acc[b] = 0.f;

    for (int kt = 0; kt < 512; kt += 64) {
        __syncthreads();
        for (int idx = t; idx < 64 * 64; idx += 128) {
            int b = idx >> 6, kk = idx & 63;
            h0s[kk * 65 + b] = g_h0[b * 512 + kt + kk];
        }
        __syncthreads();
#pragma unroll 4
        for (int kk = 0; kk < 64; kk++) {
            float w = ok ? w2c_w2[(kt + kk) * 6000 + col] : 0.f;
            const float* hrow = h0s + kk * 65;
#pragma unroll
            for (int b = 0; b < 64; b++) acc[b] = fmaf(hrow[b], w, acc[b]);
        }
    }
    if (ok) {
#pragma unroll
        for (int b = 0; b < 64; b++) g_wcode[b * 6000 + col] = acc[b] + bias;
    }
}

// ---------------------------------------------------------------------------
// Mega kernel: one block = (batch b, 64 word rows). 2 CTAs / SM.
// ---------------------------------------------------------------------------
__global__ __launch_bounds__(256, 2)
void mega_kernel(const float* __restrict__ view_cell,
                 const float* __restrict__ fc1_w,  const float* __restrict__ fc1_b,
                 const float* __restrict__ fc2_w,  const float* __restrict__ fc2_b,
                 const float* __restrict__ fca_w,  const float* __restrict__ fca_b,
                 const float* __restrict__ fce_w,  const float* __restrict__ fce_b,
                 float* __restrict__ out) {
    extern __shared__ float sm[];
    float* H    = sm + OFF_H;
    float* WT   = sm + OFF_WT;
    float* WC   = sm + OFF_WC;
    float* ACT  = sm + OFF_ACT;
    float* EMBs = sm + OFF_EMB;

    const int t    = threadIdx.x;
    const int lane = t & 31;
    const int wid  = t >> 5;
    const int b    = blockIdx.y;
    const int n0   = blockIdx.x * TR;
    const int rbase = wid * 8;

    // ---- P1: fetch precomputed wcode tile ----------------------------------
    if (t < 192) {
        int c = n0 * 3 + t;
        float w = (c < 6000) ? g_wcode[b * 6000 + c] : 0.f;
        int r = t / 3, j = t - 3 * r;
        WC[r * 4 + j] = w;
    }
    __syncthreads();

    // ---- P2: h1 = relu(wcode @ fc1_w + b1) ---------------------------------
    for (int idx = t; idx < TR * 256; idx += 256) {
        int r = idx >> 8, o = idx & 255;
        float a = fc1_b[o] + WC[r * 4 + 0] * fc1_w[o]
                           + WC[r * 4 + 1] * fc1_w[256 + o]
                           + WC[r * 4 + 2] * fc1_w[512 + o];
        H[r * HS + o] = fmaxf(a, 0.f);
    }

    // ---- P3: h2 = relu(h1 @ fc2_w + b2), FFMA2-packed ----------------------
    // warp owns rows rbase..rbase+7; lane owns col pairs 2*lane + 64*jj + {0,1}
    unsigned long long acc[8][4];
    {
        unsigned long long bv[4];
#pragma unroll
        for (int jj = 0; jj < 4; jj++)
            bv[jj] = *(const unsigned long long*)&fc2_b[2 * lane + 64 * jj];
#pragma unroll
        for (int rr = 0; rr < 8; rr++)
#pragma unroll
            for (int jj = 0; jj < 4; jj++) acc[rr][jj] = bv[jj];
    }

    for (int kt = 0; kt < 256; kt += 32) {
        __syncthreads();
        const float4* src = (const float4*)(fc2_w + kt * 256);
        float4* dst = (float4*)WT;
        for (int idx = t; idx < 2048; idx += 256) dst[idx] = src[idx];
        __syncthreads();
#pragma unroll 4
        for (int k = 0; k < 32; k++) {
            unsigned long long hp[8];
#pragma unroll
            for (int rr = 0; rr < 8; rr++)
                hp[rr] = pkdup(H[(rbase + rr) * HS + kt + k]);
#pragma unroll
            for (int jj = 0; jj < 4; jj++) {
                unsigned long long wv =
                    *(const unsigned long long*)&WT[k * 256 + 2 * lane + 64 * jj];
#pragma unroll
                for (int rr = 0; rr < 8; rr++) ffma2(acc[rr][jj], hp[rr], wv);
            }
        }
    }
    // store h2 (relu) back into H — own rows only, safe
#pragma unroll
    for (int rr = 0; rr < 8; rr++)
#pragma unroll
        for (int jj = 0; jj < 4; jj++) {
            float2 f = unpk(acc[rr][jj]);
            f.x = fmaxf(f.x, 0.f);
            f.y = fmaxf(f.y, 0.f);
            *(float2*)&H[(rbase + rr) * HS + 2 * lane + 64 * jj] = f;
        }
    __syncthreads();

    // ---- P4a: cs_emb + activation ------------------------------------------
    for (int idx = t; idx < 256 * kE; idx += 256) WT[idx] = fce_w[idx];
    __syncthreads();
    {
        float ae[8];
#pragma unroll
        for (int rr = 0; rr < 8; rr++) ae[rr] = fce_b[lane];
#pragma unroll 4
        for (int k = 0; k < 256; k++) {
            float wv = WT[k * kE + lane];
#pragma unroll
            for (int rr = 0; rr < 8; rr++)
                ae[rr] = fmaf(H[(rbase + rr) * HS + k], wv, ae[rr]);
        }
#pragma unroll
        for (int rr = 0; rr < 8; rr++) EMBs[(rbase + rr) * 33 + lane] = ae[rr];
    }
    for (int rr = 0; rr < 8; rr++) {
        int r = rbase + rr;
        const float* h2row = H + r * HS;
        float s = 0.f;
#pragma unroll
        for (int k = lane; k < 256; k += 32) s = fmaf(h2row[k], fca_w[k], s);
#pragma unroll
        for (int off = 16; off; off >>= 1) s += __shfl_xor_sync(0xffffffffu, s, off);
        if (lane == 0) ACT[r] = 1.f / (1.f + __expf(-(s + fca_b[0])));
    }
    __syncthreads();

    // ---- P4b: relation -> softmax*act -> route (into H, own rows) ----------
    for (int idx = t; idx < kE * kV; idx += 256) WT[idx] = g_vsT[idx];
    __syncthreads();
    for (int rr = 0; rr < 8; rr++) {
        int r = rbase + rr;
        float rel[8];
#pragma unroll
        for (int i = 0; i < 8; i++) rel[i] = 0.f;
#pragma unroll 4
        for (int e = 0; e < kE; e++) {
            float eb = EMBs[r * 33 + e];
#pragma unroll
            for (int i = 0; i < 8; i++)
                rel[i] = fmaf(eb, WT[e * kV + lane + 32 * i], rel[i]);
        }
        float m = rel[0];
#pragma unroll
        for (int i = 1; i < 8; i++) m = fmaxf(m, rel[i]);
#pragma unroll
        for (int off = 16; off; off >>= 1)
            m = fmaxf(m, __shfl_xor_sync(0xffffffffu, m, off));
        float s = 0.f;
#pragma unroll
        for (int i = 0; i < 8; i++) { rel[i] = __expf(rel[i] - m); s += rel[i]; }
#pragma unroll
        for (int off = 16; off; off >>= 1) s += __shfl_xor_sync(0xffffffffu, s, off);
        float scale = ACT[r] / s;
#pragma unroll
        for (int i = 0; i < 8; i++) H[r * HS + lane + 32 * i] = rel[i] * scale;
    }
    __syncthreads();

    // ---- P5: out[b,:,n0:n0+64] = view_cell[b] @ route^T, FFMA2-packed ------
    // warp owns n-rows rbase..rbase+7; lane owns c = lane*4 + {0..3} (2 pairs)
    unsigned long long pacc[2][8];
#pragma unroll
    for (int p = 0; p < 2; p++)
#pragma unroll
        for (int j = 0; j < 8; j++) pacc[p][j] = 0ull;

    const float* A = view_cell + (size_t)b * kC * kV;
    for (int v0 = 0; v0 < kV; v0 += 32) {
        __syncthreads();
        for (int idx = t; idx < kC * 32; idx += 256) {
            int c = idx >> 5, vv = idx & 31;
            WT[vv * 132 + c] = A[c * kV + v0 + vv];
        }
        __syncthreads();
#pragma unroll 4
        for (int vv = 0; vv < 32; vv++) {
            unsigned long long a0 =
                *(const unsigned long long*)&WT[vv * 132 + lane * 4];
            unsigned long long a1 =
                *(const unsigned long long*)&WT[vv * 132 + lane * 4 + 2];
#pragma unroll
            for (int j = 0; j < 8; j++) {
                unsigned long long rvp = pkdup(H[(rbase + j) * HS + v0 + vv]);
                ffma2(pacc[0][j], a0, rvp);
                ffma2(pacc[1][j], a1, rvp);
            }
        }
    }

    // stage out tile in smem for coalesced stores
    __syncthreads();
#pragma unroll
    for (int j = 0; j < 8; j++) {
        *(float2*)&WT[(rbase + j) * 132 + lane * 4]     = unpk(pacc[0][j]);
        *(float2*)&WT[(rbase + j) * 132 + lane * 4 + 2] = unpk(pacc[1][j]);
    }
    __syncthreads();
    float* outb = out + (size_t)b * kC * kN;
    for (int idx = t; idx < kC * TR; idx += 256) {
        int c = idx >> 6, rr = idx & 63;
        int n = n0 + rr;
        if (n < kN) outb[c * kN + n] = WT[rr * 132 + c];
    }
}

// ---------------------------------------------------------------------------
extern "C" void kernel_launch(void* const* d_in, const int* in_sizes, int n_in,
                              void* d_out, int out_size) {
    const float* view_cell = (const float*)d_in[0];
    const float* v         = (const float*)d_in[1];
    const float* w2c_w1    = (const float*)d_in[2];
    const float* w2c_b1    = (const float*)d_in[3];
    const float* w2c_w2    = (const float*)d_in[4];
    const float* w2c_b2    = (const float*)d_in[5];
    const float* fc1_w     = (const float*)d_in[6];
    const float* fc1_b     = (const float*)d_in[7];
    const float* fc2_w     = (const float*)d_in[8];
    const float* fc2_b     = (const float*)d_in[9];
    const float* fca_w     = (const float*)d_in[10];
    const float* fca_b     = (const float*)d_in[11];
    const float* fce_w     = (const float*)d_in[12];
    const float* fce_b     = (const float*)d_in[13];
    const float* vse_w1    = (const float*)d_in[14];
    const float* vse_b1    = (const float*)d_in[15];
    const float* vse_w2    = (const float*)d_in[16];
    const float* vse_b2    = (const float*)d_in[17];
    float* out = (float*)d_out;

    cudaFuncSetAttribute(mega_kernel, cudaFuncAttributeMaxDynamicSharedMemorySize,
                         SM_BYTES);

    setup_kernel<<<kB + 8, 512>>>(v, w2c_w1, w2c_b1, vse_w1, vse_b1, vse_w2, vse_b2);
    wcode_kernel<<<(6000 + 127) / 128, 128>>>(w2c_w2, w2c_b2);

    dim3 grid((kN + TR - 1) / TR, kB);  // (32, 64)
    mega_kernel<<<grid, 256, SM_BYTES>>>(view_cell,
                                         fc1_w, fc1_b,
                                         fc2_w, fc2_b,
                                         fca_w, fca_b,
                                         fce_w, fce_b,
                                         out);
}

// round 5
// speedup vs baseline: 1.9269x; 1.2844x over previous
#include <cuda_runtime.h>
#include <cuda_bf16.h>
#include <cstdint>

// Problem constants
constexpr int kB   = 64;     // batch
constexpr int kC   = 128;    // CSIZE
constexpr int kV   = 256;    // VIEW
constexpr int kN   = 2000;   // N_WRD
constexpr int kE   = 32;     // EMB
constexpr int TR   = 128;    // n-rows per block

// shared memory layout (float indices)
// H:    h2 (fp32) then route (fp32), 128 x 256, stride 256
// HA:   h1 as bf16, 128 rows x stride 258 bf16 (516B/row); EMB overlays after P3
// BUF:  scratch (Btile bf16 20.5KB / fce 32KB / vsT 32KB / P5 tiles)
constexpr int OFF_H   = 0;                      // 32768 floats
constexpr int OFF_HA  = 32768;                  // 16512 floats (66048 B)
constexpr int OFF_BUF = OFF_HA + 16512;         // 8192 floats
constexpr int OFF_WC  = OFF_BUF + 8192;         // 384 floats (128 x 3)
constexpr int OFF_ACT = OFF_WC + 384;           // 128
constexpr int SM_FLOATS = OFF_ACT + 128;        // 57984
constexpr int SM_BYTES  = SM_FLOATS * 4;        // 231936 B (< 227KB limit)

constexpr int HA_U32_STRIDE = 129;   // 258 bf16 per row = 129 u32
constexpr int BT_U32_STRIDE = 20;    // 40 bf16 per row  = 20 u32 (32 data + pad)

__device__ float g_h0[kB * 512];
__device__ float g_vsT[kE * kV];
__device__ float g_wcode[kB * 6000];
__device__ __align__(16) __nv_bfloat16 g_fc2bt[256 * 256];  // Bt[n][k] bf16

// ---------------- helpers ---------------------------------------------------
__device__ __forceinline__ unsigned long long pkdup(float v) {
    unsigned long long r;
    asm("mov.b64 %0, {%1, %1};" : "=l"(r) : "f"(v));
    return r;
}
__device__ __forceinline__ void ffma2(unsigned long long& d,
                                      unsigned long long a,
                                      unsigned long long b) {
    asm("fma.rn.f32x2 %0, %1, %2, %0;" : "+l"(d) : "l"(a), "l"(b));
}
__device__ __forceinline__ float2 unpk(unsigned long long v) {
    float2 f;
    asm("mov.b64 {%0, %1}, %2;" : "=f"(f.x), "=f"(f.y) : "l"(v));
    return f;
}
__device__ __forceinline__ uint32_t pack_bf16(float lo, float hi) {
    uint32_t r;
    asm("cvt.rn.bf16x2.f32 %0, %1, %2;" : "=r"(r) : "f"(hi), "f"(lo));
    return r;
}
__device__ __forceinline__ void mma_bf16(float& d0, float& d1, float& d2, float& d3,
                                         uint32_t a0, uint32_t a1, uint32_t a2, uint32_t a3,
                                         uint32_t b0, uint32_t b1) {
    asm volatile(
        "mma.sync.aligned.m16n8k16.row.col.f32.bf16.bf16.f32 "
        "{%0,%1,%2,%3}, {%4,%5,%6,%7}, {%8,%9}, {%0,%1,%2,%3};"
        : "+f"(d0), "+f"(d1), "+f"(d2), "+f"(d3)
        : "r"(a0), "r"(a1), "r"(a2), "r"(a3), "r"(b0), "r"(b1));
}

// ---------------------------------------------------------------------------
// Setup 1: h0 per batch (blocks 0..63), vsT (blocks 64..71)
// ---------------------------------------------------------------------------
__global__ void setup_kernel(const float* __restrict__ v,
                             const float* __restrict__ w2c_w1,
                             const float* __restrict__ w2c_b1,
                             const float* __restrict__ vse_w1,
                             const float* __restrict__ vse_b1,
                             const float* __restrict__ vse_w2,
                             const float* __restrict__ vse_b2) {
    int blk = blockIdx.x;
    int t = threadIdx.x;  // 512
    if (blk < kB) {
        float acc = w2c_b1[t];
#pragma unroll
        for (int i = 0; i < 7; i++) acc += v[blk * 7 + i] * w2c_w1[i * 512 + t];
        g_h0[blk * 512 + t] = fmaxf(acc, 0.f);
    } else {
        int vb = (blk - kB) * 32;
        __shared__ float hid[32][128];
        for (int idx = t; idx < 32 * 128; idx += 512) {
            int vv = idx >> 7, h = idx & 127;
            int vg = vb + vv;
            int xi = vg >> 4, yi = vg & 15;
            float x = -1.f + (2.f / 15.f) * (float)xi;
            float y = -1.f + (2.f / 15.f) * (float)yi;
            float a = x * vse_w1[h] + y * vse_w1[128 + h] + vse_b1[h];
            hid[vv][h] = fmaxf(a, 0.f);
        }
        __syncthreads();
        for (int idx = t; idx < 32 * 32; idx += 512) {
            int e = idx >> 5, vv = idx & 31;
            float acc = vse_b2[e];
#pragma unroll 8
            for (int h = 0; h < 128; h++) acc += hid[vv][h] * vse_w2[h * kE + e];
            g_vsT[e * kV + vb + vv] = acc;
        }
    }
}

// ---------------------------------------------------------------------------
// Setup 2: wcode = h0 @ w2c_w2 + b2 (w2c_w2 read once)
// ---------------------------------------------------------------------------
__global__ __launch_bounds__(128)
void wcode_kernel(const float* __restrict__ w2c_w2,
                  const float* __restrict__ w2c_b2) {
    __shared__ float h0s[64 * 65];
    int t = threadIdx.x;
    int col = blockIdx.x * 128 + t;
    bool ok = col < 6000;
    float bias = ok ? w2c_b2[col] : 0.f;

    float acc[64];
#pragma unroll
    for (int b = 0; b < 64; b++) acc[b] = 0.f;

    for (int kt = 0; kt < 512; kt += 64) {
        __syncthreads();
        for (int idx = t; idx < 64 * 64; idx += 128) {
            int b = idx >> 6, kk = idx & 63;
            h0s[kk * 65 + b] = g_h0[b * 512 + kt + kk];
        }
        __syncthreads();
#pragma unroll 4
        for (int kk = 0; kk < 64; kk++) {
            float w = ok ? w2c_w2[(kt + kk) * 6000 + col] : 0.f;
            const float* hrow = h0s + kk * 65;
#pragma unroll
            for (int b = 0; b < 64; b++) acc[b] = fmaf(hrow[b], w, acc[b]);
        }
    }
    if (ok) {
#pragma unroll
        for (int b = 0; b < 64; b++) g_wcode[b * 6000 + col] = acc[b] + bias;
    }
}

// ---------------------------------------------------------------------------
// Setup 3: transpose+convert fc2_w [k][n] fp32 -> g_fc2bt [n][k] bf16
// ---------------------------------------------------------------------------
__global__ __launch_bounds__(256)
void fc2cvt_kernel(const float* __restrict__ fc2_w) {
    int idx = blockIdx.x * 256 + threadIdx.x;  // 65536
    int k = idx >> 8, n = idx & 255;
    g_fc2bt[n * 256 + k] = __float2bfloat16(fc2_w[idx]);
}

// ---------------------------------------------------------------------------
// Mega kernel: one block = (batch b, 128 word rows). 512 threads, 1 CTA/SM.
// P3 (fc2 GEMM) on bf16 mma.sync HMMA. Everything else fp32.
// ---------------------------------------------------------------------------
__global__ __launch_bounds__(512, 1)
void mega_kernel(const float* __restrict__ view_cell,
                 const float* __restrict__ fc1_w,  const float* __restrict__ fc1_b,
                 const float* __restrict__ fc2_b,
                 const float* __restrict__ fca_w,  const float* __restrict__ fca_b,
                 const float* __restrict__ fce_w,  const float* __restrict__ fce_b,
                 float* __restrict__ out) {
    extern __shared__ float sm[];
    float*    H    = sm + OFF_H;                 // h2 then route, stride 256
    uint32_t* habu = (uint32_t*)(sm + OFF_HA);   // h1 bf16, u32 stride 129
    float*    EMBs = sm + OFF_HA;                // overlays HA after P3
    float*    BUF  = sm + OFF_BUF;
    uint32_t* btu  = (uint32_t*)(sm + OFF_BUF);  // B tile, u32 stride 20
    float*    WC   = sm + OFF_WC;
    float*    ACT  = sm + OFF_ACT;

    const int t    = threadIdx.x;
    const int lane = t & 31;
    const int wid  = t >> 5;          // 16 warps
    const int b    = blockIdx.y;
    const int n0   = blockIdx.x * TR;
    const int rbase = wid * 8;

    // ---- P1: fetch wcode tile ----------------------------------------------
    if (t < 384) {
        int c = n0 * 3 + t;
        WC[t] = (c < 6000) ? g_wcode[b * 6000 + c] : 0.f;
    }
    __syncthreads();

    // ---- P2: h1 = relu(wcode @ fc1_w + b1) -> HA (bf16 pairs) --------------
    for (int p = t; p < 128 * 128; p += 512) {
        int row = p >> 7, j = p & 127;
        float wc0 = WC[row * 3 + 0], wc1 = WC[row * 3 + 1], wc2 = WC[row * 3 + 2];
        int c0 = 2 * j;
        float f0 = fmaxf(fc1_b[c0]     + wc0 * fc1_w[c0]     + wc1 * fc1_w[256 + c0]     + wc2 * fc1_w[512 + c0],     0.f);
        float f1 = fmaxf(fc1_b[c0 + 1] + wc0 * fc1_w[c0 + 1] + wc1 * fc1_w[256 + c0 + 1] + wc2 * fc1_w[512 + c0 + 1], 0.f);
        habu[row * HA_U32_STRIDE + j] = pack_bf16(f0, f1);
    }
    __syncthreads();

    // ---- P3: h2 = relu(h1 @ fc2_w + b2) via bf16 HMMA ----------------------
    // warp (rg = wid>>1, ng = wid&1): M-rows rg*16..+15, N-cols ng*128..+127
    const int rg = wid >> 1, ng = wid & 1;
    const int m0 = rg * 16;
    const int n0w = ng * 128;
    const int qrow = lane >> 2;       // 0..7
    const int qk   = lane & 3;        // 0..3

    float d[16][4];
#pragma unroll
    for (int nt = 0; nt < 16; nt++)
#pragma unroll
        for (int i = 0; i < 4; i++) d[nt][i] = 0.f;

    for (int kc = 0; kc < 8; kc++) {
        __syncthreads();
        // copy B chunk: g_fc2bt[n][kc*32 .. +32] -> btu [n][20 u32]
        {
            int n = t >> 1, hh = t & 1;
            const uint4* src = (const uint4*)((const char*)g_fc2bt + n * 512 + kc * 64 + hh * 32);
            uint4* dst = (uint4*)((char*)btu + n * 80 + hh * 32);
            dst[0] = src[0];
            dst[1] = src[1];
        }
        __syncthreads();
#pragma unroll
        for (int ks = 0; ks < 2; ks++) {
            int kg = kc * 32 + ks * 16;
            int aidx = (m0 + qrow) * HA_U32_STRIDE + (kg >> 1) + qk;
            uint32_t a0 = habu[aidx];
            uint32_t a1 = habu[aidx + 8 * HA_U32_STRIDE];
            uint32_t a2 = habu[aidx + 4];
            uint32_t a3 = habu[aidx + 8 * HA_U32_STRIDE + 4];
#pragma unroll
            for (int nt = 0; nt < 16; nt++) {
                int c = n0w + nt * 8 + qrow;
                int bidx = c * BT_U32_STRIDE + ks * 8 + qk;
                uint32_t b0 = btu[bidx];
                uint32_t b1 = btu[bidx + 4];
                mma_bf16(d[nt][0], d[nt][1], d[nt][2], d[nt][3], a0, a1, a2, a3, b0, b1);
            }
        }
    }
    __syncthreads();
    // writeback h2 = relu(d + fc2_b) into H (fp32, stride 256)
    {
        int rlo = m0 + qrow;
#pragma unroll
        for (int nt = 0; nt < 16; nt++) {
            int c0 = n0w + nt * 8 + qk * 2;
            float bb0 = fc2_b[c0], bb1 = fc2_b[c0 + 1];
            float2 lo = make_float2(fmaxf(d[nt][0] + bb0, 0.f), fmaxf(d[nt][1] + bb1, 0.f));
            float2 hi = make_float2(fmaxf(d[nt][2] + bb0, 0.f), fmaxf(d[nt][3] + bb1, 0.f));
            *(float2*)&H[rlo * 256 + c0]       = lo;
            *(float2*)&H[(rlo + 8) * 256 + c0] = hi;
        }
    }
    __syncthreads();

    // ---- P4a: cs_emb + activation ------------------------------------------
    for (int idx = t; idx < 256 * kE; idx += 512) BUF[idx] = fce_w[idx];
    __syncthreads();
    {
        float ae[8];
#pragma unroll
        for (int rr = 0; rr < 8; rr++) ae[rr] = fce_b[lane];
#pragma unroll 4
        for (int k = 0; k < 256; k++) {
            float wv = BUF[k * kE + lane];
#pragma unroll
            for (int rr = 0; rr < 8; rr++)
                ae[rr] = fmaf(H[(rbase + rr) * 256 + k], wv, ae[rr]);
        }
#pragma unroll
        for (int rr = 0; rr < 8; rr++) EMBs[(rbase + rr) * 33 + lane] = ae[rr];
    }
    for (int rr = 0; rr < 8; rr++) {
        int r = rbase + rr;
        const float* h2row = H + r * 256;
        float s = 0.f;
#pragma unroll
        for (int k = lane; k < 256; k += 32) s = fmaf(h2row[k], fca_w[k], s);
#pragma unroll
        for (int off = 16; off; off >>= 1) s += __shfl_xor_sync(0xffffffffu, s, off);
        if (lane == 0) ACT[r] = 1.f / (1.f + __expf(-(s + fca_b[0])));
    }
    __syncthreads();

    // ---- P4b: relation -> softmax*act -> route (into H, own rows) ----------
    for (int idx = t; idx < kE * kV; idx += 512) BUF[idx] = g_vsT[idx];
    __syncthreads();
    for (int rr = 0; rr < 8; rr++) {
        int r = rbase + rr;
        float rel[8];
#pragma unroll
        for (int i = 0; i < 8; i++) rel[i] = 0.f;
#pragma unroll 4
        for (int e = 0; e < kE; e++) {
            float eb = EMBs[r * 33 + e];
#pragma unroll
            for (int i = 0; i < 8; i++)
                rel[i] = fmaf(eb, BUF[e * kV + lane + 32 * i], rel[i]);
        }
        float m = rel[0];
#pragma unroll
        for (int i = 1; i < 8; i++) m = fmaxf(m, rel[i]);
#pragma unroll
        for (int off = 16; off; off >>= 1)
            m = fmaxf(m, __shfl_xor_sync(0xffffffffu, m, off));
        float s = 0.f;
#pragma unroll
        for (int i = 0; i < 8; i++) { rel[i] = __expf(rel[i] - m); s += rel[i]; }
#pragma unroll
        for (int off = 16; off; off >>= 1) s += __shfl_xor_sync(0xffffffffu, s, off);
        float scale = ACT[r] / s;
#pragma unroll
        for (int i = 0; i < 8; i++) H[r * 256 + lane + 32 * i] = rel[i] * scale;
    }
    __syncthreads();

    // ---- P5: out[b,:,n0:n0+128] = view_cell[b] @ route^T, fp32 FFMA2 -------
    unsigned long long pacc[2][8];
#pragma unroll
    for (int p = 0; p < 2; p++)
#pragma unroll
        for (int j = 0; j < 8; j++) pacc[p][j] = 0ull;

    const float* A = view_cell + (size_t)b * kC * kV;
    for (int v0 = 0; v0 < kV; v0 += 32) {
        __syncthreads();
        for (int idx = t; idx < kC * 32; idx += 512) {
            int c = idx >> 5, vv = idx & 31;
            BUF[vv * 132 + c] = A[c * kV + v0 + vv];
        }
        __syncthreads();
#pragma unroll 4
        for (int vv = 0; vv < 32; vv++) {
            unsigned long long a0 = *(const unsigned long long*)&BUF[vv * 132 + lane * 4];
            unsigned long long a1 = *(const unsigned long long*)&BUF[vv * 132 + lane * 4 + 2];
#pragma unroll
            for (int j = 0; j < 8; j++) {
                unsigned long long rvp = pkdup(H[(rbase + j) * 256 + v0 + vv]);
                ffma2(pacc[0][j], a0, rvp);
                ffma2(pacc[1][j], a1, rvp);
            }
        }
    }

    // stage + store in four 32-row quarters
    float* outb = out + (size_t)b * kC * kN;
#pragma unroll
    for (int q = 0; q < 4; q++) {
        __syncthreads();
        if ((wid >> 2) == q) {
            int lr = (wid & 3) * 8;
#pragma unroll
            for (int j = 0; j < 8; j++) {
                *(float2*)&BUF[(lr + j) * 132 + lane * 4]     = unpk(pacc[0][j]);
                *(float2*)&BUF[(lr + j) * 132 + lane * 4 + 2] = unpk(pacc[1][j]);
            }
        }
        __syncthreads();
        for (int idx = t; idx < kC * 32; idx += 512) {
            int c = idx >> 5, rr = idx & 31;
            int n = n0 + q * 32 + rr;
            if (n < kN) outb[c * kN + n] = BUF[rr * 132 + c];
        }
    }
}

// ---------------------------------------------------------------------------
extern "C" void kernel_launch(void* const* d_in, const int* in_sizes, int n_in,
                              void* d_out, int out_size) {
    const float* view_cell = (const float*)d_in[0];
    const float* v         = (const float*)d_in[1];
    const float* w2c_w1    = (const float*)d_in[2];
    const float* w2c_b1    = (const float*)d_in[3];
    const float* w2c_w2    = (const float*)d_in[4];
    const float* w2c_b2    = (const float*)d_in[5];
    const float* fc1_w     = (const float*)d_in[6];
    const float* fc1_b     = (const float*)d_in[7];
    const float* fc2_w     = (const float*)d_in[8];
    const float* fc2_b     = (const float*)d_in[9];
    const float* fca_w     = (const float*)d_in[10];
    const float* fca_b     = (const float*)d_in[11];
    const float* fce_w     = (const float*)d_in[12];
    const float* fce_b     = (const float*)d_in[13];
    const float* vse_w1    = (const float*)d_in[14];
    const float* vse_b1    = (const float*)d_in[15];
    const float* vse_w2    = (const float*)d_in[16];
    const float* vse_b2    = (const float*)d_in[17];
    float* out = (float*)d_out;

    cudaFuncSetAttribute(mega_kernel, cudaFuncAttributeMaxDynamicSharedMemorySize,
                         SM_BYTES);

    setup_kernel<<<kB + 8, 512>>>(v, w2c_w1, w2c_b1, vse_w1, vse_b1, vse_w2, vse_b2);
    wcode_kernel<<<(6000 + 127) / 128, 128>>>(w2c_w2, w2c_b2);
    fc2cvt_kernel<<<256, 256>>>(fc2_w);

    dim3 grid((kN + TR - 1) / TR, kB);  // (16, 64)
    mega_kernel<<<grid, 512, SM_BYTES>>>(view_cell,
                                         fc1_w, fc1_b, fc2_b,
                                         fca_w, fca_b,
                                         fce_w, fce_b,
                                         out);
}

// round 8
// speedup vs baseline: 2.4686x; 1.2811x over previous
#include <cuda_runtime.h>
#include <cuda_bf16.h>
#include <cstdint>

// Problem constants
constexpr int kB   = 64;     // batch
constexpr int kC   = 128;    // CSIZE
constexpr int kV   = 256;    // VIEW
constexpr int kN   = 2000;   // N_WRD
constexpr int kE   = 32;     // EMB
constexpr int TR   = 128;    // n-rows per block

// shared memory layout (float indices)
constexpr int OFF_H   = 0;                      // 32768: relation then route, fp32 128x256
constexpr int OFF_HA  = 32768;                  // 16512: h1 then h2 bf16, 128 x 129 u32
constexpr int OFF_BUF = OFF_HA + 16512;         // 5184: Btile / fceT / vsT / P5 tiles
constexpr int OFF_EMB = OFF_BUF + 5184;         // 2176: emb bf16, 128 x 17 u32
constexpr int OFF_WC  = OFF_EMB + 2176;         // 384
constexpr int OFF_ACT = OFF_WC + 384;           // 128
constexpr int SM_FLOATS = OFF_ACT + 128;        // 57152
constexpr int SM_BYTES  = SM_FLOATS * 4;        // 228608 B

constexpr int HA_U32_STRIDE  = 129;  // 258 bf16 per row
constexpr int BT_U32_STRIDE  = 20;   // P3 B tile rows (32 bf16 + pad)
constexpr int FCE_U32_STRIDE = 132;  // fceT tile rows (256 bf16 + pad)
constexpr int VST_U32_STRIDE = 17;   // vsT tile rows (32 bf16 + pad)
constexpr int EMB_U32_STRIDE = 17;   // emb rows (32 bf16 + pad)

__device__ float g_h0[kB * 512];
__device__ float g_wcode[kB * 6000];
__device__ __align__(16) __nv_bfloat16 g_fc2bt[256 * 256];  // fc2 Bt[n][k]
__device__ __align__(16) __nv_bfloat16 g_fceT[32 * 256];    // fce Bt[n][k]
__device__ __align__(16) __nv_bfloat16 g_vsTbf[256 * 32];   // vs [v][e]

// ---------------- helpers ---------------------------------------------------
__device__ __forceinline__ unsigned long long pkdup(float v) {
    unsigned long long r;
    asm("mov.b64 %0, {%1, %1};" : "=l"(r) : "f"(v));
    return r;
}
__device__ __forceinline__ void ffma2(unsigned long long& d,
                                      unsigned long long a,
                                      unsigned long long b) {
    asm("fma.rn.f32x2 %0, %1, %2, %0;" : "+l"(d) : "l"(a), "l"(b));
}
__device__ __forceinline__ float2 unpk(unsigned long long v) {
    float2 f;
    asm("mov.b64 {%0, %1}, %2;" : "=f"(f.x), "=f"(f.y) : "l"(v));
    return f;
}
__device__ __forceinline__ uint32_t pack_bf16(float lo, float hi) {
    uint32_t r;
    asm("cvt.rn.bf16x2.f32 %0, %1, %2;" : "=r"(r) : "f"(hi), "f"(lo));
    return r;
}
__device__ __forceinline__ float bf16lo(uint32_t u) { return __uint_as_float(u << 16); }
__device__ __forceinline__ float bf16hi(uint32_t u) { return __uint_as_float(u & 0xffff0000u); }
__device__ __forceinline__ void mma_bf16(float& d0, float& d1, float& d2, float& d3,
                                         uint32_t a0, uint32_t a1, uint32_t a2, uint32_t a3,
                                         uint32_t b0, uint32_t b1) {
    asm volatile(
        "mma.sync.aligned.m16n8k16.row.col.f32.bf16.bf16.f32 "
        "{%0,%1,%2,%3}, {%4,%5,%6,%7}, {%8,%9}, {%0,%1,%2,%3};"
        : "+f"(d0), "+f"(d1), "+f"(d2), "+f"(d3)
        : "r"(a0), "r"(a1), "r"(a2), "r"(a3), "r"(b0), "r"(b1));
}

// ---------------------------------------------------------------------------
// Setup 1: h0 per batch (blocks 0..63), vsTbf (blocks 64..71)
// ---------------------------------------------------------------------------
__global__ void setup_kernel(const float* __restrict__ v,
                             const float* __restrict__ w2c_w1,
                             const float* __restrict__ w2c_b1,
                             const float* __restrict__ vse_w1,
                             const float* __restrict__ vse_b1,
                             const float* __restrict__ vse_w2,
                             const float* __restrict__ vse_b2) {
    int blk = blockIdx.x;
    int t = threadIdx.x;  // 512
    if (blk < kB) {
        float acc = w2c_b1[t];
#pragma unroll
        for (int i = 0; i < 7; i++) acc += v[blk * 7 + i] * w2c_w1[i * 512 + t];
        g_h0[blk * 512 + t] = fmaxf(acc, 0.f);
    } else {
        int vb = (blk - kB) * 32;
        __shared__ float hid[32][128];
        for (int idx = t; idx < 32 * 128; idx += 512) {
            int vv = idx >> 7, h = idx & 127;
            int vg = vb + vv;
            int xi = vg >> 4, yi = vg & 15;
            float x = -1.f + (2.f / 15.f) * (float)xi;
            float y = -1.f + (2.f / 15.f) * (float)yi;
            float a = x * vse_w1[h] + y * vse_w1[128 + h] + vse_b1[h];
            hid[vv][h] = fmaxf(a, 0.f);
        }
        __syncthreads();
        for (int idx = t; idx < 32 * 32; idx += 512) {
            int e = idx >> 5, vv = idx & 31;
            float acc = vse_b2[e];
#pragma unroll 8
            for (int h = 0; h < 128; h++) acc += hid[vv][h] * vse_w2[h * kE + e];
            g_vsTbf[(vb + vv) * 32 + e] = __float2bfloat16(acc);
        }
    }
}

// ---------------------------------------------------------------------------
// Setup 2: wcode = h0 @ w2c_w2 + b2 (w2c_w2 read once)
// ---------------------------------------------------------------------------
__global__ __launch_bounds__(128)
void wcode_kernel(const float* __restrict__ w2c_w2,
                  const float* __restrict__ w2c_b2) {
    __shared__ float h0s[64 * 65];
    int t = threadIdx.x;
    int col = blockIdx.x * 128 + t;
    bool ok = col < 6000;
    float bias = ok ? w2c_b2[col] : 0.f;

    float acc[64];
#pragma unroll
    for (int b = 0; b < 64; b++) acc[b] = 0.f;

    for (int kt = 0; kt < 512; kt += 64) {
        __syncthreads();
        for (int idx = t; idx < 64 * 64; idx += 128) {
            int b = idx >> 6, kk = idx & 63;
            h0s[kk * 65 + b] = g_h0[b * 512 + kt + kk];
        }
        __syncthreads();
#pragma unroll 4
        for (int kk = 0; kk < 64; kk++) {
            float w = ok ? w2c_w2[(kt + kk) * 6000 + col] : 0.f;
            const float* hrow = h0s + kk * 65;
#pragma unroll
            for (int b = 0; b < 64; b++) acc[b] = fmaf(hrow[b], w, acc[b]);
        }
    }
    if (ok) {
#pragma unroll
        for (int b = 0; b < 64; b++) g_wcode[b * 6000 + col] = acc[b] + bias;
    }
}

// ---------------------------------------------------------------------------
// Setup 3: fc2_w -> g_fc2bt (transpose+bf16); fce_w -> g_fceT
// ---------------------------------------------------------------------------
__global__ __launch_bounds__(256)
void cvt_kernel(const float* __restrict__ fc2_w, const float* __restrict__ fce_w) {
    int blk = blockIdx.x;
    int t = threadIdx.x;
    if (blk < 256) {
        int idx = blk * 256 + t;  // 65536
        int k = idx >> 8, n = idx & 255;
        g_fc2bt[n * 256 + k] = __float2bfloat16(fc2_w[idx]);
    } else {
        int idx = (blk - 256) * 256 + t;  // 8192
        int k = idx >> 5, n = idx & 31;
        g_fceT[n * 256 + k] = __float2bfloat16(fce_w[idx]);
    }
}

// ---------------------------------------------------------------------------
// Mega kernel: one block = (batch b, 128 word rows). 512 threads, 1 CTA/SM.
// P3/P4a/P4b on bf16 HMMA; P5 fp32 FFMA2.
// ---------------------------------------------------------------------------
__global__ __launch_bounds__(512, 1)
void mega_kernel(const float* __restrict__ view_cell,
                 const float* __restrict__ fc1_w,  const float* __restrict__ fc1_b,
                 const float* __restrict__ fc2_b,
                 const float* __restrict__ fca_w,  const float* __restrict__ fca_b,
                 const float* __restrict__ fce_b,
                 float* __restrict__ out) {
    extern __shared__ float sm[];
    float*    H    = sm + OFF_H;                 // relation -> route, stride 256
    uint32_t* habu = (uint32_t*)(sm + OFF_HA);   // h1/h2 bf16, u32 stride 129
    float*    BUF  = sm + OFF_BUF;
    uint32_t* bufu = (uint32_t*)(sm + OFF_BUF);
    uint32_t* embu = (uint32_t*)(sm + OFF_EMB);  // emb bf16, u32 stride 17
    float*    WC   = sm + OFF_WC;
    float*    ACT  = sm + OFF_ACT;

    const int t    = threadIdx.x;
    const int lane = t & 31;
    const int wid  = t >> 5;          // 16 warps
    const int b    = blockIdx.y;
    const int n0   = blockIdx.x * TR;
    const int rbase = wid * 8;
    const int qrow = lane >> 2;       // 0..7
    const int qk   = lane & 3;        // 0..3

    // ---- P1: fetch wcode tile ----------------------------------------------
    if (t < 384) {
        int c = n0 * 3 + t;
        WC[t] = (c < 6000) ? g_wcode[b * 6000 + c] : 0.f;
    }
    __syncthreads();

    // ---- P2: h1 = relu(wcode @ fc1_w + b1) -> HA (bf16 pairs) --------------
    for (int p = t; p < 128 * 128; p += 512) {
        int row = p >> 7, j = p & 127;
        float wc0 = WC[row * 3 + 0], wc1 = WC[row * 3 + 1], wc2 = WC[row * 3 + 2];
        int c0 = 2 * j;
        float f0 = fmaxf(fc1_b[c0]     + wc0 * fc1_w[c0]     + wc1 * fc1_w[256 + c0]     + wc2 * fc1_w[512 + c0],     0.f);
        float f1 = fmaxf(fc1_b[c0 + 1] + wc0 * fc1_w[c0 + 1] + wc1 * fc1_w[256 + c0 + 1] + wc2 * fc1_w[512 + c0 + 1], 0.f);
        habu[row * HA_U32_STRIDE + j] = pack_bf16(f0, f1);
    }
    __syncthreads();

    // ---- P3: h2 = relu(h1 @ fc2_w + b2) via bf16 HMMA ----------------------
    const int rg = wid >> 1, ng = wid & 1;
    const int m0 = rg * 16;
    const int n0w = ng * 128;

    float d[16][4];
#pragma unroll
    for (int nt = 0; nt < 16; nt++)
#pragma unroll
        for (int i = 0; i < 4; i++) d[nt][i] = 0.f;

    for (int kc = 0; kc < 8; kc++) {
        __syncthreads();
        {   // copy B chunk: g_fc2bt[n][kc*32..+32] -> bufu [n][20 u32]
            int n = t >> 1, hh = t & 1;
            const uint4* src = (const uint4*)((const char*)g_fc2bt + n * 512 + kc * 64 + hh * 32);
            uint4* dst = (uint4*)((char*)bufu + n * 80 + hh * 32);
            dst[0] = src[0];
            dst[1] = src[1];
        }
        __syncthreads();
#pragma unroll
        for (int ks = 0; ks < 2; ks++) {
            int kg = kc * 32 + ks * 16;
            int aidx = (m0 + qrow) * HA_U32_STRIDE + (kg >> 1) + qk;
            uint32_t a0 = habu[aidx];
            uint32_t a1 = habu[aidx + 8 * HA_U32_STRIDE];
            uint32_t a2 = habu[aidx + 4];
            uint32_t a3 = habu[aidx + 8 * HA_U32_STRIDE + 4];
#pragma unroll
            for (int nt = 0; nt < 16; nt++) {
                int c = n0w + nt * 8 + qrow;
                int bidx = c * BT_U32_STRIDE + ks * 8 + qk;
                mma_bf16(d[nt][0], d[nt][1], d[nt][2], d[nt][3],
                         a0, a1, a2, a3, bufu[bidx], bufu[bidx + 4]);
            }
        }
    }
    __syncthreads();
    // writeback h2 = relu(d + fc2_b) as bf16 into HA (h1 dead)
    {
        int rlo = m0 + qrow;
#pragma unroll
        for (int nt = 0; nt < 16; nt++) {
            int c0 = n0w + nt * 8 + qk * 2;
            float bb0 = fc2_b[c0], bb1 = fc2_b[c0 + 1];
            int ucol = (c0 >> 1);
            habu[rlo * HA_U32_STRIDE + ucol] =
                pack_bf16(fmaxf(d[nt][0] + bb0, 0.f), fmaxf(d[nt][1] + bb1, 0.f));
            habu[(rlo + 8) * HA_U32_STRIDE + ucol] =
                pack_bf16(fmaxf(d[nt][2] + bb0, 0.f), fmaxf(d[nt][3] + bb1, 0.f));
        }
    }
    // load fceT tile into BUF (32 n x 256 k bf16, u32 stride 132)
    for (int idx = t; idx < 32 * 128; idx += 512) {
        int n = idx >> 7, j = idx & 127;
        bufu[n * FCE_U32_STRIDE + j] = ((const uint32_t*)g_fceT)[n * 128 + j];
    }
    __syncthreads();

    // ---- P4a: emb = h2 @ fce_w + fce_b via HMMA (M=128,N=32,K=256) ---------
    {
        float e[2][4];
#pragma unroll
        for (int nt = 0; nt < 2; nt++)
#pragma unroll
            for (int i = 0; i < 4; i++) e[nt][i] = 0.f;
#pragma unroll
        for (int ks = 0; ks < 16; ks++) {
            int aidx = (m0 + qrow) * HA_U32_STRIDE + ks * 8 + qk;
            uint32_t a0 = habu[aidx];
            uint32_t a1 = habu[aidx + 8 * HA_U32_STRIDE];
            uint32_t a2 = habu[aidx + 4];
            uint32_t a3 = habu[aidx + 8 * HA_U32_STRIDE + 4];
#pragma unroll
            for (int nt = 0; nt < 2; nt++) {
                int n = ng * 16 + nt * 8 + qrow;
                int bidx = n * FCE_U32_STRIDE + ks * 8 + qk;
                mma_bf16(e[nt][0], e[nt][1], e[nt][2], e[nt][3],
                         a0, a1, a2, a3, bufu[bidx], bufu[bidx + 4]);
            }
        }
        // add bias, pack to EMB bf16
#pragma unroll
        for (int nt = 0; nt < 2; nt++) {
            int c0 = ng * 16 + nt * 8 + qk * 2;
            float bb0 = fce_b[c0], bb1 = fce_b[c0 + 1];
            int ucol = ng * 8 + nt * 4 + qk;
            embu[(m0 + qrow) * EMB_U32_STRIDE + ucol] =
                pack_bf16(e[nt][0] + bb0, e[nt][1] + bb1);
            embu[(m0 + qrow + 8) * EMB_U32_STRIDE + ucol] =
                pack_bf16(e[nt][2] + bb0, e[nt][3] + bb1);
        }
    }
    // ---- act: sigmoid(h2 . fca_w + b) from bf16 h2 (own rows, warp-local) --
    {
        float2 w2[4];
#pragma unroll
        for (int i = 0; i < 4; i++) w2[i] = ((const float2*)fca_w)[lane + 32 * i];
        for (int rr = 0; rr < 8; rr++) {
            int r = rbase + rr;
            float s = 0.f;
#pragma unroll
            for (int i = 0; i < 4; i++) {
                uint32_t hv = habu[r * HA_U32_STRIDE + lane + 32 * i];
                s = fmaf(bf16lo(hv), w2[i].x, s);
                s = fmaf(bf16hi(hv), w2[i].y, s);
            }
#pragma unroll
            for (int off = 16; off; off >>= 1) s += __shfl_xor_sync(0xffffffffu, s, off);
            if (lane == 0) ACT[r] = 1.f / (1.f + __expf(-(s + fca_b[0])));
        }
    }
    __syncthreads();

    // load vsT tile into BUF (256 v x 32 e bf16, u32 stride 17)
    for (int idx = t; idx < 256 * 16; idx += 512) {
        int n = idx >> 4, j = idx & 15;
        bufu[n * VST_U32_STRIDE + j] = ((const uint32_t*)g_vsTbf)[n * 16 + j];
    }
    __syncthreads();

    // ---- P4b: relation = emb @ vsT^T via HMMA (M=128,N=256,K=32) -----------
    {
        const int vg = ng;  // reuse wid&1 as v-half
#pragma unroll
        for (int nt = 0; nt < 16; nt++)
#pragma unroll
            for (int i = 0; i < 4; i++) d[nt][i] = 0.f;
#pragma unroll
        for (int ks = 0; ks < 2; ks++) {
            int aidx = (m0 + qrow) * EMB_U32_STRIDE + ks * 8 + qk;
            uint32_t a0 = embu[aidx];
            uint32_t a1 = embu[aidx + 8 * EMB_U32_STRIDE];
            uint32_t a2 = embu[aidx + 4];
            uint32_t a3 = embu[aidx + 8 * EMB_U32_STRIDE + 4];
#pragma unroll
            for (int nt = 0; nt < 16; nt++) {
                int n = vg * 128 + nt * 8 + qrow;
                int bidx = n * VST_U32_STRIDE + ks * 8 + qk;
                mma_bf16(d[nt][0], d[nt][1], d[nt][2], d[nt][3],
                         a0, a1, a2, a3, bufu[bidx], bufu[bidx + 4]);
            }
        }
        // write relation fp32 to H
        int rlo = m0 + qrow;
#pragma unroll
        for (int nt = 0; nt < 16; nt++) {
            int c0 = vg * 128 + nt * 8 + qk * 2;
            *(float2*)&H[rlo * 256 + c0]       = make_float2(d[nt][0], d[nt][1]);
            *(float2*)&H[(rlo + 8) * 256 + c0] = make_float2(d[nt][2], d[nt][3]);
        }
    }
    __syncthreads();

    // ---- softmax * act over H rows (warp = 8 rows) -------------------------
    for (int rr = 0; rr < 8; rr++) {
        int r = rbase + rr;
        float4 ra = *(float4*)&H[r * 256 + lane * 8];
        float4 rb = *(float4*)&H[r * 256 + lane * 8 + 4];
        float m = fmaxf(fmaxf(fmaxf(ra.x, ra.y), fmaxf(ra.z, ra.w)),
                        fmaxf(fmaxf(rb.x, rb.y), fmaxf(rb.z, rb.w)));
#pragma unroll
        for (int off = 16; off; off >>= 1)
            m = fmaxf(m, __shfl_xor_sync(0xffffffffu, m, off));
        ra.x = __expf(ra.x - m); ra.y = __expf(ra.y - m);
        ra.z = __expf(ra.z - m); ra.w = __expf(ra.w - m);
        rb.x = __expf(rb.x - m); rb.y = __expf(rb.y - m);
        rb.z = __expf(rb.z - m); rb.w = __expf(rb.w - m);
        float s = ra.x + ra.y + ra.z + ra.w + rb.x + rb.y + rb.z + rb.w;
#pragma unroll
        for (int off = 16; off; off >>= 1) s += __shfl_xor_sync(0xffffffffu, s, off);
        float sc = ACT[r] / s;
        ra.x *= sc; ra.y *= sc; ra.z *= sc; ra.w *= sc;
        rb.x *= sc; rb.y *= sc; rb.z *= sc; rb.w *= sc;
        *(float4*)&H[r * 256 + lane * 8]     = ra;
        *(float4*)&H[r * 256 + lane * 8 + 4] = rb;
    }
    __syncthreads();

    // ---- P5: out[b,:,n0:n0+128] = view_cell[b] @ route^T, fp32 FFMA2 -------
    unsigned long long pacc[2][8];
#pragma unroll
    for (int p = 0; p < 2; p++)
#pragma unroll
        for (int j = 0; j < 8; j++) pacc[p][j] = 0ull;

    const float* A = view_cell + (size_t)b * kC * kV;
    for (int v0 = 0; v0 < kV; v0 += 32) {
        __syncthreads();
        for (int idx = t; idx < kC * 32; idx += 512) {
            int c = idx >> 5, vv = idx & 31;
            BUF[vv * 132 + c] = A[c * kV + v0 + vv];
        }
        __syncthreads();
#pragma unroll 4
        for (int vv = 0; vv < 32; vv++) {
            unsigned long long a0 = *(const unsigned long long*)&BUF[vv * 132 + lane * 4];
            unsigned long long a1 = *(const unsigned long long*)&BUF[vv * 132 + lane * 4 + 2];
#pragma unroll
            for (int j = 0; j < 8; j++) {
                unsigned long long rvp = pkdup(H[(rbase + j) * 256 + v0 + vv]);
                ffma2(pacc[0][j], a0, rvp);
                ffma2(pacc[1][j], a1, rvp);
            }
        }
    }

    // stage + store in four 32-row quarters
    float* outb = out + (size_t)b * kC * kN;
#pragma unroll
    for (int q = 0; q < 4; q++) {
        __syncthreads();
        if ((wid >> 2) == q) {
            int lr = (wid & 3) * 8;
#pragma unroll
            for (int j = 0; j < 8; j++) {
                *(float2*)&BUF[(lr + j) * 132 + lane * 4]     = unpk(pacc[0][j]);
                *(float2*)&BUF[(lr + j) * 132 + lane * 4 + 2] = unpk(pacc[1][j]);
            }
        }
        __syncthreads();
        for (int idx = t; idx < kC * 32; idx += 512) {
            int c = idx >> 5, rr = idx & 31;
            int n = n0 + q * 32 + rr;
            if (n < kN) outb[c * kN + n] = BUF[rr * 132 + c];
        }
    }
}

// ---------------------------------------------------------------------------
extern "C" void kernel_launch(void* const* d_in, const int* in_sizes, int n_in,
                              void* d_out, int out_size) {
    const float* view_cell = (const float*)d_in[0];
    const float* v         = (const float*)d_in[1];
    const float* w2c_w1    = (const float*)d_in[2];
    const float* w2c_b1    = (const float*)d_in[3];
    const float* w2c_w2    = (const float*)d_in[4];
    const float* w2c_b2    = (const float*)d_in[5];
    const float* fc1_w     = (const float*)d_in[6];
    const float* fc1_b     = (const float*)d_in[7];
    const float* fc2_w     = (const float*)d_in[8];
    const float* fc2_b     = (const float*)d_in[9];
    const float* fca_w     = (const float*)d_in[10];
    const float* fca_b     = (const float*)d_in[11];
    const float* fce_w     = (const float*)d_in[12];
    const float* fce_b     = (const float*)d_in[13];
    const float* vse_w1    = (const float*)d_in[14];
    const float* vse_b1    = (const float*)d_in[15];
    const float* vse_w2    = (const float*)d_in[16];
    const float* vse_b2    = (const float*)d_in[17];
    float* out = (float*)d_out;

    cudaFuncSetAttribute(mega_kernel, cudaFuncAttributeMaxDynamicSharedMemorySize,
                         SM_BYTES);

    setup_kernel<<<kB + 8, 512>>>(v, w2c_w1, w2c_b1, vse_w1, vse_b1, vse_w2, vse_b2);
    wcode_kernel<<<(6000 + 127) / 128, 128>>>(w2c_w2, w2c_b2);
    cvt_kernel<<<288, 256>>>(fc2_w, fce_w);

    dim3 grid((kN + TR - 1) / TR, kB);  // (16, 64)
    mega_kernel<<<grid, 512, SM_BYTES>>>(view_cell,
                                         fc1_w, fc1_b, fc2_b,
                                         fca_w, fca_b, fce_b,
                                         out);
}

// round 9
// speedup vs baseline: 3.0112x; 1.2198x over previous
#include <cuda_runtime.h>
#include <cuda_bf16.h>
#include <cstdint>

// Problem constants
constexpr int kB   = 64;     // batch
constexpr int kC   = 128;    // CSIZE
constexpr int kV   = 256;    // VIEW
constexpr int kN   = 2000;   // N_WRD
constexpr int kE   = 32;     // EMB
constexpr int TR   = 128;    // n-rows per block

// shared memory layout (float indices)
constexpr int OFF_H   = 0;                      // 32768: relation then route, fp32 128x256
constexpr int OFF_HA  = 32768;                  // 16512: h1/h2 bf16; P5 tiles overlay
constexpr int OFF_BUF = OFF_HA + 16512;         // 5184: Btile / fceT / vsT
constexpr int OFF_EMB = OFF_BUF + 5184;         // 2176: emb bf16, 128 x 17 u32
constexpr int OFF_WC  = OFF_EMB + 2176;         // 384
constexpr int OFF_ACT = OFF_WC + 384;           // 128
constexpr int SM_FLOATS = OFF_ACT + 128;        // 57152
constexpr int SM_BYTES  = SM_FLOATS * 4;        // 228608 B

constexpr int HA_U32_STRIDE  = 129;  // 258 bf16 per row
constexpr int BT_U32_STRIDE  = 20;   // P3 B tile rows (32 bf16 + pad)
constexpr int FCE_U32_STRIDE = 132;  // fceT tile rows (256 bf16 + pad)
constexpr int VST_U32_STRIDE = 17;   // vsT tile rows (32 bf16 + pad)
constexpr int EMB_U32_STRIDE = 17;   // emb rows (32 bf16 + pad)
constexpr int P5_STRIDE      = 36;   // P5 tiles: 64 bf16 = 32 u32 + 4 pad

__device__ float g_h0[kB * 512];
__device__ float g_wcode[kB * 6000];
__device__ __align__(16) __nv_bfloat16 g_fc2bt[256 * 256];  // fc2 Bt[n][k]
__device__ __align__(16) __nv_bfloat16 g_fceT[32 * 256];    // fce Bt[n][k]
__device__ __align__(16) __nv_bfloat16 g_vsTbf[256 * 32];   // vs [v][e]
__device__ __align__(16) __nv_bfloat16 g_vchi[kB * kC * kV]; // view_cell hi
__device__ __align__(16) __nv_bfloat16 g_vclo[kB * kC * kV]; // view_cell lo

// ---------------- helpers ---------------------------------------------------
__device__ __forceinline__ uint32_t pack_bf16(float lo, float hi) {
    uint32_t r;
    asm("cvt.rn.bf16x2.f32 %0, %1, %2;" : "=r"(r) : "f"(hi), "f"(lo));
    return r;
}
__device__ __forceinline__ float bf16lo(uint32_t u) { return __uint_as_float(u << 16); }
__device__ __forceinline__ float bf16hi(uint32_t u) { return __uint_as_float(u & 0xffff0000u); }
__device__ __forceinline__ void mma_bf16(float& d0, float& d1, float& d2, float& d3,
                                         uint32_t a0, uint32_t a1, uint32_t a2, uint32_t a3,
                                         uint32_t b0, uint32_t b1) {
    asm volatile(
        "mma.sync.aligned.m16n8k16.row.col.f32.bf16.bf16.f32 "
        "{%0,%1,%2,%3}, {%4,%5,%6,%7}, {%8,%9}, {%0,%1,%2,%3};"
        : "+f"(d0), "+f"(d1), "+f"(d2), "+f"(d3)
        : "r"(a0), "r"(a1), "r"(a2), "r"(a3), "r"(b0), "r"(b1));
}

// ---------------------------------------------------------------------------
// Setup 1: h0 per batch (blocks 0..63), vsTbf (blocks 64..71)
// ---------------------------------------------------------------------------
__global__ void setup_kernel(const float* __restrict__ v,
                             const float* __restrict__ w2c_w1,
                             const float* __restrict__ w2c_b1,
                             const float* __restrict__ vse_w1,
                             const float* __restrict__ vse_b1,
                             const float* __restrict__ vse_w2,
                             const float* __restrict__ vse_b2) {
    int blk = blockIdx.x;
    int t = threadIdx.x;  // 512
    if (blk < kB) {
        float acc = w2c_b1[t];
#pragma unroll
        for (int i = 0; i < 7; i++) acc += v[blk * 7 + i] * w2c_w1[i * 512 + t];
        g_h0[blk * 512 + t] = fmaxf(acc, 0.f);
    } else {
        int vb = (blk - kB) * 32;
        __shared__ float hid[32][128];
        for (int idx = t; idx < 32 * 128; idx += 512) {
            int vv = idx >> 7, h = idx & 127;
            int vg = vb + vv;
            int xi = vg >> 4, yi = vg & 15;
            float x = -1.f + (2.f / 15.f) * (float)xi;
            float y = -1.f + (2.f / 15.f) * (float)yi;
            float a = x * vse_w1[h] + y * vse_w1[128 + h] + vse_b1[h];
            hid[vv][h] = fmaxf(a, 0.f);
        }
        __syncthreads();
        for (int idx = t; idx < 32 * 32; idx += 512) {
            int e = idx >> 5, vv = idx & 31;
            float acc = vse_b2[e];
#pragma unroll 8
            for (int h = 0; h < 128; h++) acc += hid[vv][h] * vse_w2[h * kE + e];
            g_vsTbf[(vb + vv) * 32 + e] = __float2bfloat16(acc);
        }
    }
}

// ---------------------------------------------------------------------------
// Setup 2: wcode = h0 @ w2c_w2 + b2 (w2c_w2 read once)
// ---------------------------------------------------------------------------
__global__ __launch_bounds__(128)
void wcode_kernel(const float* __restrict__ w2c_w2,
                  const float* __restrict__ w2c_b2) {
    __shared__ float h0s[64 * 65];
    int t = threadIdx.x;
    int col = blockIdx.x * 128 + t;
    bool ok = col < 6000;
    float bias = ok ? w2c_b2[col] : 0.f;

    float acc[64];
#pragma unroll
    for (int b = 0; b < 64; b++) acc[b] = 0.f;

    for (int kt = 0; kt < 512; kt += 64) {
        __syncthreads();
        for (int idx = t; idx < 64 * 64; idx += 128) {
            int b = idx >> 6, kk = idx & 63;
            h0s[kk * 65 + b] = g_h0[b * 512 + kt + kk];
        }
        __syncthreads();
#pragma unroll 4
        for (int kk = 0; kk < 64; kk++) {
            float w = ok ? w2c_w2[(kt + kk) * 6000 + col] : 0.f;
            const float* hrow = h0s + kk * 65;
#pragma unroll
            for (int b = 0; b < 64; b++) acc[b] = fmaf(hrow[b], w, acc[b]);
        }
    }
    if (ok) {
#pragma unroll
        for (int b = 0; b < 64; b++) g_wcode[b * 6000 + col] = acc[b] + bias;
    }
}

// ---------------------------------------------------------------------------
// Setup 3: fc2_w -> g_fc2bt (transpose+bf16); fce_w -> g_fceT
// ---------------------------------------------------------------------------
__global__ __launch_bounds__(256)
void cvt_kernel(const float* __restrict__ fc2_w, const float* __restrict__ fce_w) {
    int blk = blockIdx.x;
    int t = threadIdx.x;
    if (blk < 256) {
        int idx = blk * 256 + t;  // 65536
        int k = idx >> 8, n = idx & 255;
        g_fc2bt[n * 256 + k] = __float2bfloat16(fc2_w[idx]);
    } else {
        int idx = (blk - 256) * 256 + t;  // 8192
        int k = idx >> 5, n = idx & 31;
        g_fceT[n * 256 + k] = __float2bfloat16(fce_w[idx]);
    }
}

// ---------------------------------------------------------------------------
// Setup 4: view_cell fp32 -> hi/lo bf16 pair arrays (same [b][c][v] layout)
// ---------------------------------------------------------------------------
__global__ __launch_bounds__(512)
void vccvt_kernel(const float* __restrict__ view_cell) {
    int p = blockIdx.x * 512 + threadIdx.x;   // pair index, 1048576 pairs
    float2 f = ((const float2*)view_cell)[p];
    uint32_t h = pack_bf16(f.x, f.y);
    float r0 = f.x - bf16lo(h);
    float r1 = f.y - bf16hi(h);
    ((uint32_t*)g_vchi)[p] = h;
    ((uint32_t*)g_vclo)[p] = pack_bf16(r0, r1);
}

// ---------------------------------------------------------------------------
// Mega kernel: one block = (batch b, 128 word rows). 512 threads, 1 CTA/SM.
// P3/P4a/P4b bf16 HMMA; P5 split-bf16 HMMA (3-product emulation).
// ---------------------------------------------------------------------------
__global__ __launch_bounds__(512, 1)
void mega_kernel(const float* __restrict__ fc1_w,  const float* __restrict__ fc1_b,
                 const float* __restrict__ fc2_b,
                 const float* __restrict__ fca_w,  const float* __restrict__ fca_b,
                 const float* __restrict__ fce_b,
                 float* __restrict__ out) {
    extern __shared__ float sm[];
    float*    H    = sm + OFF_H;                 // relation -> route, stride 256
    uint32_t* habu = (uint32_t*)(sm + OFF_HA);   // h1/h2 bf16, u32 stride 129
    float*    BUF  = sm + OFF_BUF;
    uint32_t* bufu = (uint32_t*)(sm + OFF_BUF);
    uint32_t* embu = (uint32_t*)(sm + OFF_EMB);  // emb bf16, u32 stride 17
    float*    WC   = sm + OFF_WC;
    float*    ACT  = sm + OFF_ACT;
    // P5 tile overlay (HA region onwards): Ahi, Alo, Bhi, Blo — 4 x 128 x 36 u32
    uint32_t* AH = (uint32_t*)(sm + OFF_HA);
    uint32_t* AL = AH + 128 * P5_STRIDE;
    uint32_t* BH = AL + 128 * P5_STRIDE;
    uint32_t* BL = BH + 128 * P5_STRIDE;        // ends at +18432 u32 < 23872 avail

    const int t    = threadIdx.x;
    const int lane = t & 31;
    const int wid  = t >> 5;          // 16 warps
    const int b    = blockIdx.y;
    const int n0   = blockIdx.x * TR;
    const int rbase = wid * 8;
    const int qrow = lane >> 2;       // 0..7
    const int qk   = lane & 3;        // 0..3

    // ---- P1: fetch wcode tile ----------------------------------------------
    if (t < 384) {
        int c = n0 * 3 + t;
        WC[t] = (c < 6000) ? g_wcode[b * 6000 + c] : 0.f;
    }
    __syncthreads();

    // ---- P2: h1 = relu(wcode @ fc1_w + b1) -> HA (bf16 pairs) --------------
    for (int p = t; p < 128 * 128; p += 512) {
        int row = p >> 7, j = p & 127;
        float wc0 = WC[row * 3 + 0], wc1 = WC[row * 3 + 1], wc2 = WC[row * 3 + 2];
        int c0 = 2 * j;
        float f0 = fmaxf(fc1_b[c0]     + wc0 * fc1_w[c0]     + wc1 * fc1_w[256 + c0]     + wc2 * fc1_w[512 + c0],     0.f);
        float f1 = fmaxf(fc1_b[c0 + 1] + wc0 * fc1_w[c0 + 1] + wc1 * fc1_w[256 + c0 + 1] + wc2 * fc1_w[512 + c0 + 1], 0.f);
        habu[row * HA_U32_STRIDE + j] = pack_bf16(f0, f1);
    }
    __syncthreads();

    // ---- P3: h2 = relu(h1 @ fc2_w + b2) via bf16 HMMA ----------------------
    const int rg = wid >> 1, ng = wid & 1;
    const int m0 = rg * 16;
    const int n0w = ng * 128;

    float d[16][4];
#pragma unroll
    for (int nt = 0; nt < 16; nt++)
#pragma unroll
        for (int i = 0; i < 4; i++) d[nt][i] = 0.f;

    for (int kc = 0; kc < 8; kc++) {
        __syncthreads();
        {   // copy B chunk: g_fc2bt[n][kc*32..+32] -> bufu [n][20 u32]
            int n = t >> 1, hh = t & 1;
            const uint4* src = (const uint4*)((const char*)g_fc2bt + n * 512 + kc * 64 + hh * 32);
            uint4* dst = (uint4*)((char*)bufu + n * 80 + hh * 32);
            dst[0] = src[0];
            dst[1] = src[1];
        }
        __syncthreads();
#pragma unroll
        for (int ks = 0; ks < 2; ks++) {
            int kg = kc * 32 + ks * 16;
            int aidx = (m0 + qrow) * HA_U32_STRIDE + (kg >> 1) + qk;
            uint32_t a0 = habu[aidx];
            uint32_t a1 = habu[aidx + 8 * HA_U32_STRIDE];
            uint32_t a2 = habu[aidx + 4];
            uint32_t a3 = habu[aidx + 8 * HA_U32_STRIDE + 4];
#pragma unroll
            for (int nt = 0; nt < 16; nt++) {
                int c = n0w + nt * 8 + qrow;
                int bidx = c * BT_U32_STRIDE + ks * 8 + qk;
                mma_bf16(d[nt][0], d[nt][1], d[nt][2], d[nt][3],
                         a0, a1, a2, a3, bufu[bidx], bufu[bidx + 4]);
            }
        }
    }
    __syncthreads();
    // writeback h2 = relu(d + fc2_b) as bf16 into HA (h1 dead)
    {
        int rlo = m0 + qrow;
#pragma unroll
        for (int nt = 0; nt < 16; nt++) {
            int c0 = n0w + nt * 8 + qk * 2;
            float bb0 = fc2_b[c0], bb1 = fc2_b[c0 + 1];
            int ucol = (c0 >> 1);
            habu[rlo * HA_U32_STRIDE + ucol] =
                pack_bf16(fmaxf(d[nt][0] + bb0, 0.f), fmaxf(d[nt][1] + bb1, 0.f));
            habu[(rlo + 8) * HA_U32_STRIDE + ucol] =
                pack_bf16(fmaxf(d[nt][2] + bb0, 0.f), fmaxf(d[nt][3] + bb1, 0.f));
        }
    }
    // load fceT tile into BUF (32 n x 256 k bf16, u32 stride 132)
    for (int idx = t; idx < 32 * 128; idx += 512) {
        int n = idx >> 7, j = idx & 127;
        bufu[n * FCE_U32_STRIDE + j] = ((const uint32_t*)g_fceT)[n * 128 + j];
    }
    __syncthreads();

    // ---- P4a: emb = h2 @ fce_w + fce_b via HMMA (M=128,N=32,K=256) ---------
    {
        float e[2][4];
#pragma unroll
        for (int nt = 0; nt < 2; nt++)
#pragma unroll
            for (int i = 0; i < 4; i++) e[nt][i] = 0.f;
#pragma unroll
        for (int ks = 0; ks < 16; ks++) {
            int aidx = (m0 + qrow) * HA_U32_STRIDE + ks * 8 + qk;
            uint32_t a0 = habu[aidx];
            uint32_t a1 = habu[aidx + 8 * HA_U32_STRIDE];
            uint32_t a2 = habu[aidx + 4];
            uint32_t a3 = habu[aidx + 8 * HA_U32_STRIDE + 4];
#pragma unroll
            for (int nt = 0; nt < 2; nt++) {
                int n = ng * 16 + nt * 8 + qrow;
                int bidx = n * FCE_U32_STRIDE + ks * 8 + qk;
                mma_bf16(e[nt][0], e[nt][1], e[nt][2], e[nt][3],
                         a0, a1, a2, a3, bufu[bidx], bufu[bidx + 4]);
            }
        }
#pragma unroll
        for (int nt = 0; nt < 2; nt++) {
            int c0 = ng * 16 + nt * 8 + qk * 2;
            float bb0 = fce_b[c0], bb1 = fce_b[c0 + 1];
            int ucol = ng * 8 + nt * 4 + qk;
            embu[(m0 + qrow) * EMB_U32_STRIDE + ucol] =
                pack_bf16(e[nt][0] + bb0, e[nt][1] + bb1);
            embu[(m0 + qrow + 8) * EMB_U32_STRIDE + ucol] =
                pack_bf16(e[nt][2] + bb0, e[nt][3] + bb1);
        }
    }
    // ---- act: sigmoid(h2 . fca_w + b) from bf16 h2 (own rows) --------------
    {
        float2 w2[4];
#pragma unroll
        for (int i = 0; i < 4; i++) w2[i] = ((const float2*)fca_w)[lane + 32 * i];
        for (int rr = 0; rr < 8; rr++) {
            int r = rbase + rr;
            float s = 0.f;
#pragma unroll
            for (int i = 0; i < 4; i++) {
                uint32_t hv = habu[r * HA_U32_STRIDE + lane + 32 * i];
                s = fmaf(bf16lo(hv), w2[i].x, s);
                s = fmaf(bf16hi(hv), w2[i].y, s);
            }
#pragma unroll
            for (int off = 16; off; off >>= 1) s += __shfl_xor_sync(0xffffffffu, s, off);
            if (lane == 0) ACT[r] = 1.f / (1.f + __expf(-(s + fca_b[0])));
        }
    }
    __syncthreads();

    // load vsT tile into BUF (256 v x 32 e bf16, u32 stride 17)
    for (int idx = t; idx < 256 * 16; idx += 512) {
        int n = idx >> 4, j = idx & 15;
        bufu[n * VST_U32_STRIDE + j] = ((const uint32_t*)g_vsTbf)[n * 16 + j];
    }
    __syncthreads();

    // ---- P4b: relation = emb @ vsT^T via HMMA (M=128,N=256,K=32) -----------
    {
        const int vg = ng;
#pragma unroll
        for (int nt = 0; nt < 16; nt++)
#pragma unroll
            for (int i = 0; i < 4; i++) d[nt][i] = 0.f;
#pragma unroll
        for (int ks = 0; ks < 2; ks++) {
            int aidx = (m0 + qrow) * EMB_U32_STRIDE + ks * 8 + qk;
            uint32_t a0 = embu[aidx];
            uint32_t a1 = embu[aidx + 8 * EMB_U32_STRIDE];
            uint32_t a2 = embu[aidx + 4];
            uint32_t a3 = embu[aidx + 8 * EMB_U32_STRIDE + 4];
#pragma unroll
            for (int nt = 0; nt < 16; nt++) {
                int n = vg * 128 + nt * 8 + qrow;
                int bidx = n * VST_U32_STRIDE + ks * 8 + qk;
                mma_bf16(d[nt][0], d[nt][1], d[nt][2], d[nt][3],
                         a0, a1, a2, a3, bufu[bidx], bufu[bidx + 4]);
            }
        }
        int rlo = m0 + qrow;
#pragma unroll
        for (int nt = 0; nt < 16; nt++) {
            int c0 = vg * 128 + nt * 8 + qk * 2;
            *(float2*)&H[rlo * 256 + c0]       = make_float2(d[nt][0], d[nt][1]);
            *(float2*)&H[(rlo + 8) * 256 + c0] = make_float2(d[nt][2], d[nt][3]);
        }
    }
    __syncthreads();

    // ---- softmax * act over H rows (warp = 8 rows) -------------------------
    for (int rr = 0; rr < 8; rr++) {
        int r = rbase + rr;
        float4 ra = *(float4*)&H[r * 256 + lane * 8];
        float4 rb = *(float4*)&H[r * 256 + lane * 8 + 4];
        float m = fmaxf(fmaxf(fmaxf(ra.x, ra.y), fmaxf(ra.z, ra.w)),
                        fmaxf(fmaxf(rb.x, rb.y), fmaxf(rb.z, rb.w)));
#pragma unroll
        for (int off = 16; off; off >>= 1)
            m = fmaxf(m, __shfl_xor_sync(0xffffffffu, m, off));
        ra.x = __expf(ra.x - m); ra.y = __expf(ra.y - m);
        ra.z = __expf(ra.z - m); ra.w = __expf(ra.w - m);
        rb.x = __expf(rb.x - m); rb.y = __expf(rb.y - m);
        rb.z = __expf(rb.z - m); rb.w = __expf(rb.w - m);
        float s = ra.x + ra.y + ra.z + ra.w + rb.x + rb.y + rb.z + rb.w;
#pragma unroll
        for (int off = 16; off; off >>= 1) s += __shfl_xor_sync(0xffffffffu, s, off);
        float sc = ACT[r] / s;
        ra.x *= sc; ra.y *= sc; ra.z *= sc; ra.w *= sc;
        rb.x *= sc; rb.y *= sc; rb.z *= sc; rb.w *= sc;
        *(float4*)&H[r * 256 + lane * 8]     = ra;
        *(float4*)&H[r * 256 + lane * 8 + 4] = rb;
    }
    __syncthreads();

    // ---- P5: out[b,:,n0:n0+128] = view_cell[b] @ route^T -------------------
    // split-bf16 HMMA: acc = Ahi*Bhi + Ahi*Blo + Alo*Bhi (fp32 accum)
    // warp grid 4x4: wm = c-rows wm*32..+31, wn = n-cols wn*32..+31
    const int wm = wid >> 2, wn = wid & 3;
    float p5d[2][4][4];
#pragma unroll
    for (int mt = 0; mt < 2; mt++)
#pragma unroll
        for (int ntl = 0; ntl < 4; ntl++)
#pragma unroll
            for (int i = 0; i < 4; i++) p5d[mt][ntl][i] = 0.f;

    for (int vc = 0; vc < 4; vc++) {          // v-chunk of 64
        const int v0 = vc * 64;
        __syncthreads();
        // stage A hi/lo from global ([b][c][256] bf16; chunk = 32 u32/row)
        {
            const uint4* sh = (const uint4*)((const uint32_t*)g_vchi + b * 16384 + (v0 >> 1));
            const uint4* sl = (const uint4*)((const uint32_t*)g_vclo + b * 16384 + (v0 >> 1));
            // row stride in uint4: 128 u32 = 32 uint4; chunk = 8 uint4
            for (int i = t; i < 1024; i += 512) {
                int c = i >> 3, j = i & 7;
                *(uint4*)&AH[c * P5_STRIDE + j * 4] = sh[c * 32 + j];
                *(uint4*)&AL[c * P5_STRIDE + j * 4] = sl[c * 32 + j];
            }
        }
        // convert route chunk fp32 -> hi/lo bf16 (128 n-rows x 64 v)
        {
            int n = t >> 2, seg = t & 3;       // 16 v per thread
            const float* src = H + n * 256 + v0 + seg * 16;
            uint32_t* dh = BH + n * P5_STRIDE + seg * 8;
            uint32_t* dl = BL + n * P5_STRIDE + seg * 8;
#pragma unroll
            for (int j = 0; j < 8; j++) {
                float f0 = src[2 * j], f1 = src[2 * j + 1];
                uint32_t h = pack_bf16(f0, f1);
                dh[j] = h;
                dl[j] = pack_bf16(f0 - bf16lo(h), f1 - bf16hi(h));
            }
        }
        __syncthreads();
#pragma unroll
        for (int ks = 0; ks < 4; ks++) {
            uint32_t ah[2][4], al[2][4];
#pragma unroll
            for (int mt = 0; mt < 2; mt++) {
                int row = wm * 32 + mt * 16 + qrow;
                int aidx = row * P5_STRIDE + ks * 8 + qk;
                ah[mt][0] = AH[aidx];
                ah[mt][1] = AH[aidx + 8 * P5_STRIDE];
                ah[mt][2] = AH[aidx + 4];
                ah[mt][3] = AH[aidx + 8 * P5_STRIDE + 4];
                al[mt][0] = AL[aidx];
                al[mt][1] = AL[aidx + 8 * P5_STRIDE];
                al[mt][2] = AL[aidx + 4];
                al[mt][3] = AL[aidx + 8 * P5_STRIDE + 4];
            }
#pragma unroll
            for (int ntl = 0; ntl < 4; ntl++) {
                int n = wn * 32 + ntl * 8 + qrow;
                int bidx = n * P5_STRIDE + ks * 8 + qk;
                uint32_t bh0 = BH[bidx], bh1 = BH[bidx + 4];
                uint32_t bl0 = BL[bidx], bl1 = BL[bidx + 4];
#pragma unroll
                for (int mt = 0; mt < 2; mt++) {
                    mma_bf16(p5d[mt][ntl][0], p5d[mt][ntl][1], p5d[mt][ntl][2], p5d[mt][ntl][3],
                             ah[mt][0], ah[mt][1], ah[mt][2], ah[mt][3], bh0, bh1);
                    mma_bf16(p5d[mt][ntl][0], p5d[mt][ntl][1], p5d[mt][ntl][2], p5d[mt][ntl][3],
                             ah[mt][0], ah[mt][1], ah[mt][2], ah[mt][3], bl0, bl1);
                    mma_bf16(p5d[mt][ntl][0], p5d[mt][ntl][1], p5d[mt][ntl][2], p5d[mt][ntl][3],
                             al[mt][0], al[mt][1], al[mt][2], al[mt][3], bh0, bh1);
                }
            }
        }
    }

    // direct predicated stores: out[b][c][n], n contiguous
    float* outb = out + (size_t)b * kC * kN;
#pragma unroll
    for (int mt = 0; mt < 2; mt++) {
        int row = wm * 32 + mt * 16 + qrow;
        float* o0 = outb + (size_t)row * kN;
        float* o1 = o0 + 8 * kN;
#pragma unroll
        for (int ntl = 0; ntl < 4; ntl++) {
            int col = n0 + wn * 32 + ntl * 8 + qk * 2;
            if (col < kN) {
                *(float2*)&o0[col] = make_float2(p5d[mt][ntl][0], p5d[mt][ntl][1]);
                *(float2*)&o1[col] = make_float2(p5d[mt][ntl][2], p5d[mt][ntl][3]);
            }
        }
    }
}

// ---------------------------------------------------------------------------
extern "C" void kernel_launch(void* const* d_in, const int* in_sizes, int n_in,
                              void* d_out, int out_size) {
    const float* view_cell = (const float*)d_in[0];
    const float* v         = (const float*)d_in[1];
    const float* w2c_w1    = (const float*)d_in[2];
    const float* w2c_b1    = (const float*)d_in[3];
    const float* w2c_w2    = (const float*)d_in[4];
    const float* w2c_b2    = (const float*)d_in[5];
    const float* fc1_w     = (const float*)d_in[6];
    const float* fc1_b     = (const float*)d_in[7];
    const float* fc2_w     = (const float*)d_in[8];
    const float* fc2_b     = (const float*)d_in[9];
    const float* fca_w     = (const float*)d_in[10];
    const float* fca_b     = (const float*)d_in[11];
    const float* fce_w     = (const float*)d_in[12];
    const float* fce_b     = (const float*)d_in[13];
    const float* vse_w1    = (const float*)d_in[14];
    const float* vse_b1    = (const float*)d_in[15];
    const float* vse_w2    = (const float*)d_in[16];
    const float* vse_b2    = (const float*)d_in[17];
    float* out = (float*)d_out;

    cudaFuncSetAttribute(mega_kernel, cudaFuncAttributeMaxDynamicSharedMemorySize,
                         SM_BYTES);

    setup_kernel<<<kB + 8, 512>>>(v, w2c_w1, w2c_b1, vse_w1, vse_b1, vse_w2, vse_b2);
    wcode_kernel<<<(6000 + 127) / 128, 128>>>(w2c_w2, w2c_b2);
    cvt_kernel<<<288, 256>>>(fc2_w, fce_w);
    vccvt_kernel<<<2048, 512>>>(view_cell);   // 1M float2 pairs

    dim3 grid((kN + TR - 1) / TR, kB);  // (16, 64)
    mega_kernel<<<grid, 512, SM_BYTES>>>(fc1_w, fc1_b, fc2_b,
                                         fca_w, fca_b, fce_b,
                                         out);
}

// round 14
// speedup vs baseline: 3.7302x; 1.2388x over previous
#include <cuda_runtime.h>
#include <cuda_bf16.h>
#include <cstdint>

// Problem constants
constexpr int kB   = 64;     // batch
constexpr int kC   = 128;    // CSIZE
constexpr int kV   = 256;    // VIEW
constexpr int kN   = 2000;   // N_WRD
constexpr int kE   = 32;     // EMB
constexpr int TR   = 128;    // n-rows per block

// shared memory layout (float indices)
constexpr int OFF_H   = 0;                      // 32768: relation then route, fp32 128x256
constexpr int OFF_HA  = 32768;                  // 16512: h1/h2 bf16; P5 tiles overlay
constexpr int OFF_BUF = OFF_HA + 16512;         // 5184: Btile / fceT / vsT
constexpr int OFF_EMB = OFF_BUF + 5184;         // 2176: emb bf16, 128 x 17 u32
constexpr int OFF_WC  = OFF_EMB + 2176;         // 384
constexpr int OFF_ACT = OFF_WC + 384;           // 128
constexpr int SM_FLOATS = OFF_ACT + 128;        // 57152
constexpr int SM_BYTES  = SM_FLOATS * 4;        // 228608 B

constexpr int HA_U32_STRIDE  = 129;  // 258 bf16 per row
constexpr int BT_U32_STRIDE  = 20;   // P3 B tile rows (32 bf16 + pad)
constexpr int FCE_U32_STRIDE = 132;  // fceT tile rows (256 bf16 + pad)
constexpr int VST_U32_STRIDE = 17;   // vsT tile rows (32 bf16 + pad)
constexpr int EMB_U32_STRIDE = 17;   // emb rows (32 bf16 + pad)
constexpr int P5_STRIDE      = 36;   // P5 tiles: 64 bf16 = 32 u32 + 4 pad

__device__ float g_h0[kB * 512];
__device__ float g_wcode[kB * 6000];
__device__ __align__(16) __nv_bfloat16 g_fc2bt[256 * 256];  // fc2 Bt[n][k]
__device__ __align__(16) __nv_bfloat16 g_fceT[32 * 256];    // fce Bt[n][k]
__device__ __align__(16) __nv_bfloat16 g_vsTbf[256 * 32];   // vs [v][e]
__device__ __align__(16) __nv_bfloat16 g_vchi[kB * kC * kV]; // view_cell hi
__device__ __align__(16) __nv_bfloat16 g_vclo[kB * kC * kV]; // view_cell lo

// ---------------- helpers ---------------------------------------------------
__device__ __forceinline__ uint32_t pack_bf16(float lo, float hi) {
    uint32_t r;
    asm("cvt.rn.bf16x2.f32 %0, %1, %2;" : "=r"(r) : "f"(hi), "f"(lo));
    return r;
}
__device__ __forceinline__ float bf16lo(uint32_t u) { return __uint_as_float(u << 16); }
__device__ __forceinline__ float bf16hi(uint32_t u) { return __uint_as_float(u & 0xffff0000u); }
__device__ __forceinline__ void mma_bf16(float& d0, float& d1, float& d2, float& d3,
                                         uint32_t a0, uint32_t a1, uint32_t a2, uint32_t a3,
                                         uint32_t b0, uint32_t b1) {
    asm volatile(
        "mma.sync.aligned.m16n8k16.row.col.f32.bf16.bf16.f32 "
        "{%0,%1,%2,%3}, {%4,%5,%6,%7}, {%8,%9}, {%0,%1,%2,%3};"
        : "+f"(d0), "+f"(d1), "+f"(d2), "+f"(d3)
        : "r"(a0), "r"(a1), "r"(a2), "r"(a3), "r"(b0), "r"(b1));
}

// ---------------------------------------------------------------------------
// Prep kernel (merged): all independent setup work in ONE launch.
//   blocks [0,64):      h0 per batch
//   blocks [64,72):     vsTbf
//   blocks [72,84):     g_wcode bias init (g_wcode[b][col] = w2c_b2[col])
//   blocks [84,340):    fc2 transpose+bf16 cvt
//   blocks [340,372):   fce transpose+bf16 cvt
//   blocks [372,2420):  view_cell hi/lo split
// ---------------------------------------------------------------------------
__global__ __launch_bounds__(512)
void prep_kernel(const float* __restrict__ v,
                 const float* __restrict__ w2c_w1,
                 const float* __restrict__ w2c_b1,
                 const float* __restrict__ w2c_b2,
                 const float* __restrict__ vse_w1,
                 const float* __restrict__ vse_b1,
                 const float* __restrict__ vse_w2,
                 const float* __restrict__ vse_b2,
                 const float* __restrict__ fc2_w,
                 const float* __restrict__ fce_w,
                 const float* __restrict__ view_cell) {
    int blk = blockIdx.x;
    int t = threadIdx.x;  // 512
    if (blk < 64) {
        float acc = w2c_b1[t];
#pragma unroll
        for (int i = 0; i < 7; i++) acc += v[blk * 7 + i] * w2c_w1[i * 512 + t];
        g_h0[blk * 512 + t] = fmaxf(acc, 0.f);
    } else if (blk < 72) {
        int vb = (blk - 64) * 32;
        __shared__ float hid[32][128];
        for (int idx = t; idx < 32 * 128; idx += 512) {
            int vv = idx >> 7, h = idx & 127;
            int vg = vb + vv;
            int xi = vg >> 4, yi = vg & 15;
            float x = -1.f + (2.f / 15.f) * (float)xi;
            float y = -1.f + (2.f / 15.f) * (float)yi;
            float a = x * vse_w1[h] + y * vse_w1[128 + h] + vse_b1[h];
            hid[vv][h] = fmaxf(a, 0.f);
        }
        __syncthreads();
        for (int idx = t; idx < 32 * 32; idx += 512) {
            int e = idx >> 5, vv = idx & 31;
            float acc = vse_b2[e];
#pragma unroll 8
            for (int h = 0; h < 128; h++) acc += hid[vv][h] * vse_w2[h * kE + e];
            g_vsTbf[(vb + vv) * 32 + e] = __float2bfloat16(acc);
        }
    } else if (blk < 84) {
        // bias-init g_wcode: 384000 elems over 12 blocks x 512 threads
        for (int i = (blk - 72) * 512 + t; i < kB * 6000; i += 12 * 512) {
            int col = i % 6000;
            g_wcode[i] = w2c_b2[col];
        }
    } else if (blk < 340) {
        int idx = (blk - 84) * 256;
        // two halves of 256 threads each handle 256 elems? keep 512-thread map:
        int p = idx * 2 + t;          // wrong scale guard below
        // simpler: each block handles 512 consecutive elems of 65536*? recompute:
        // fc2: 65536 elems over 256 blocks -> 256 elems/block... use 512 threads,
        // half idle is fine; map p in [0,65536):
        p = (blk - 84) * 256 + (t & 255);
        if (t < 256) {
            int k = p >> 8, n = p & 255;
            g_fc2bt[n * 256 + k] = __float2bfloat16(fc2_w[p]);
        }
    } else if (blk < 372) {
        int p = (blk - 340) * 256 + (t & 255);  // 8192 elems over 32 blocks
        if (t < 256) {
            int k = p >> 5, n = p & 31;
            g_fceT[n * 256 + k] = __float2bfloat16(fce_w[p]);
        }
    } else {
        int p = (blk - 372) * 512 + t;   // pair index, 1048576 pairs
        float2 f = ((const float2*)view_cell)[p];
        uint32_t h = pack_bf16(f.x, f.y);
        ((uint32_t*)g_vchi)[p] = h;
        ((uint32_t*)g_vclo)[p] = pack_bf16(f.x - bf16lo(h), f.y - bf16hi(h));
    }
}

// ---------------------------------------------------------------------------
// wcode: k-split GEMM with atomic accumulation.
// block (cb, ks): cols cb*128 + t, k-chunk ks*64..+64; adds into g_wcode.
// ---------------------------------------------------------------------------
__global__ __launch_bounds__(128)
void wcode_kernel(const float* __restrict__ w2c_w2) {
    __shared__ float h0s[64 * 65];  // [kk][b]
    int t = threadIdx.x;
    int col = blockIdx.x * 128 + t;
    int k0 = blockIdx.y * 64;
    bool ok = col < 6000;

    for (int idx = t; idx < 64 * 64; idx += 128) {
        int b = idx >> 6, kk = idx & 63;
        h0s[kk * 65 + b] = g_h0[b * 512 + k0 + kk];
    }
    __syncthreads();

    float acc[64];
#pragma unroll
    for (int b = 0; b < 64; b++) acc[b] = 0.f;
#pragma unroll 4
    for (int kk = 0; kk < 64; kk++) {
        float w = ok ? w2c_w2[(k0 + kk) * 6000 + col] : 0.f;
        const float* hrow = h0s + kk * 65;
#pragma unroll
        for (int b = 0; b < 64; b++) acc[b] = fmaf(hrow[b], w, acc[b]);
    }
    if (ok) {
#pragma unroll
        for (int b = 0; b < 64; b++) atomicAdd(&g_wcode[b * 6000 + col], acc[b]);
    }
}

// ---------------------------------------------------------------------------
// Mega kernel: one block = (batch b, 128 word rows). 512 threads, 1 CTA/SM.
// P3/P4a/P4b bf16 HMMA; P5 split-bf16 HMMA (3-product emulation).
// ---------------------------------------------------------------------------
__global__ __launch_bounds__(512, 1)
void mega_kernel(const float* __restrict__ fc1_w,  const float* __restrict__ fc1_b,
                 const float* __restrict__ fc2_b,
                 const float* __restrict__ fca_w,  const float* __restrict__ fca_b,
                 const float* __restrict__ fce_b,
                 float* __restrict__ out) {
    extern __shared__ float sm[];
    float*    H    = sm + OFF_H;                 // relation -> route, stride 256
    uint32_t* habu = (uint32_t*)(sm + OFF_HA);   // h1/h2 bf16, u32 stride 129
    float*    BUF  = sm + OFF_BUF;
    uint32_t* bufu = (uint32_t*)(sm + OFF_BUF);
    uint32_t* embu = (uint32_t*)(sm + OFF_EMB);  // emb bf16, u32 stride 17
    float*    WC   = sm + OFF_WC;
    float*    ACT  = sm + OFF_ACT;
    // P5 tile overlay (HA region onwards): Ahi, Alo, Bhi, Blo — 4 x 128 x 36 u32
    uint32_t* AH = (uint32_t*)(sm + OFF_HA);
    uint32_t* AL = AH + 128 * P5_STRIDE;
    uint32_t* BH = AL + 128 * P5_STRIDE;
    uint32_t* BL = BH + 128 * P5_STRIDE;

    const int t    = threadIdx.x;
    const int lane = t & 31;
    const int wid  = t >> 5;          // 16 warps
    const int b    = blockIdx.y;
    const int n0   = blockIdx.x * TR;
    const int rbase = wid * 8;
    const int qrow = lane >> 2;       // 0..7
    const int qk   = lane & 3;        // 0..3

    // ---- P1: fetch wcode tile ----------------------------------------------
    if (t < 384) {
        int c = n0 * 3 + t;
        WC[t] = (c < 6000) ? g_wcode[b * 6000 + c] : 0.f;
    }
    __syncthreads();

    // ---- P2: h1 = relu(wcode @ fc1_w + b1) -> HA (bf16 pairs) --------------
    for (int p = t; p < 128 * 128; p += 512) {
        int row = p >> 7, j = p & 127;
        float wc0 = WC[row * 3 + 0], wc1 = WC[row * 3 + 1], wc2 = WC[row * 3 + 2];
        int c0 = 2 * j;
        float f0 = fmaxf(fc1_b[c0]     + wc0 * fc1_w[c0]     + wc1 * fc1_w[256 + c0]     + wc2 * fc1_w[512 + c0],     0.f);
        float f1 = fmaxf(fc1_b[c0 + 1] + wc0 * fc1_w[c0 + 1] + wc1 * fc1_w[256 + c0 + 1] + wc2 * fc1_w[512 + c0 + 1], 0.f);
        habu[row * HA_U32_STRIDE + j] = pack_bf16(f0, f1);
    }
    __syncthreads();

    // ---- P3: h2 = relu(h1 @ fc2_w + b2) via bf16 HMMA ----------------------
    const int rg = wid >> 1, ng = wid & 1;
    const int m0 = rg * 16;
    const int n0w = ng * 128;

    float d[16][4];
#pragma unroll
    for (int nt = 0; nt < 16; nt++)
#pragma unroll
        for (int i = 0; i < 4; i++) d[nt][i] = 0.f;

    for (int kc = 0; kc < 8; kc++) {
        __syncthreads();
        {   // copy B chunk: g_fc2bt[n][kc*32..+32] -> bufu [n][20 u32]
            int n = t >> 1, hh = t & 1;
            const uint4* src = (const uint4*)((const char*)g_fc2bt + n * 512 + kc * 64 + hh * 32);
            uint4* dst = (uint4*)((char*)bufu + n * 80 + hh * 32);
            dst[0] = src[0];
            dst[1] = src[1];
        }
        __syncthreads();
#pragma unroll
        for (int ks = 0; ks < 2; ks++) {
            int kg = kc * 32 + ks * 16;
            int aidx = (m0 + qrow) * HA_U32_STRIDE + (kg >> 1) + qk;
            uint32_t a0 = habu[aidx];
            uint32_t a1 = habu[aidx + 8 * HA_U32_STRIDE];
            uint32_t a2 = habu[aidx + 4];
            uint32_t a3 = habu[aidx + 8 * HA_U32_STRIDE + 4];
#pragma unroll
            for (int nt = 0; nt < 16; nt++) {
                int c = n0w + nt * 8 + qrow;
                int bidx = c * BT_U32_STRIDE + ks * 8 + qk;
                mma_bf16(d[nt][0], d[nt][1], d[nt][2], d[nt][3],
                         a0, a1, a2, a3, bufu[bidx], bufu[bidx + 4]);
            }
        }
    }
    __syncthreads();
    // writeback h2 = relu(d + fc2_b) as bf16 into HA (h1 dead)
    {
        int rlo = m0 + qrow;
#pragma unroll
        for (int nt = 0; nt < 16; nt++) {
            int c0 = n0w + nt * 8 + qk * 2;
            float bb0 = fc2_b[c0], bb1 = fc2_b[c0 + 1];
            int ucol = (c0 >> 1);
            habu[rlo * HA_U32_STRIDE + ucol] =
                pack_bf16(fmaxf(d[nt][0] + bb0, 0.f), fmaxf(d[nt][1] + bb1, 0.f));
            habu[(rlo + 8) * HA_U32_STRIDE + ucol] =
                pack_bf16(fmaxf(d[nt][2] + bb0, 0.f), fmaxf(d[nt][3] + bb1, 0.f));
        }
    }
    // load fceT tile into BUF (32 n x 256 k bf16, u32 stride 132)
    for (int idx = t; idx < 32 * 128; idx += 512) {
        int n = idx >> 7, j = idx & 127;
        bufu[n * FCE_U32_STRIDE + j] = ((const uint32_t*)g_fceT)[n * 128 + j];
    }
    __syncthreads();

    // ---- P4a: emb = h2 @ fce_w + fce_b via HMMA (M=128,N=32,K=256) ---------
    {
        float e[2][4];
#pragma unroll
        for (int nt = 0; nt < 2; nt++)
#pragma unroll
            for (int i = 0; i < 4; i++) e[nt][i] = 0.f;
#pragma unroll
        for (int ks = 0; ks < 16; ks++) {
            int aidx = (m0 + qrow) * HA_U32_STRIDE + ks * 8 + qk;
            uint32_t a0 = habu[aidx];
            uint32_t a1 = habu[aidx + 8 * HA_U32_STRIDE];
            uint32_t a2 = habu[aidx + 4];
            uint32_t a3 = habu[aidx + 8 * HA_U32_STRIDE + 4];
#pragma unroll
            for (int nt = 0; nt < 2; nt++) {
                int n = ng * 16 + nt * 8 + qrow;
                int bidx = n * FCE_U32_STRIDE + ks * 8 + qk;
                mma_bf16(e[nt][0], e[nt][1], e[nt][2], e[nt][3],
                         a0, a1, a2, a3, bufu[bidx], bufu[bidx + 4]);
            }
        }
#pragma unroll
        for (int nt = 0; nt < 2; nt++) {
            int c0 = ng * 16 + nt * 8 + qk * 2;
            float bb0 = fce_b[c0], bb1 = fce_b[c0 + 1];
            int ucol = ng * 8 + nt * 4 + qk;
            embu[(m0 + qrow) * EMB_U32_STRIDE + ucol] =
                pack_bf16(e[nt][0] + bb0, e[nt][1] + bb1);
            embu[(m0 + qrow + 8) * EMB_U32_STRIDE + ucol] =
                pack_bf16(e[nt][2] + bb0, e[nt][3] + bb1);
        }
    }
    // ---- act: sigmoid(h2 . fca_w + b) from bf16 h2 (own rows) --------------
    {
        float2 w2[4];
#pragma unroll
        for (int i = 0; i < 4; i++) w2[i] = ((const float2*)fca_w)[lane + 32 * i];
        for (int rr = 0; rr < 8; rr++) {
            int r = rbase + rr;
            float s = 0.f;
#pragma unroll
            for (int i = 0; i < 4; i++) {
                uint32_t hv = habu[r * HA_U32_STRIDE + lane + 32 * i];
                s = fmaf(bf16lo(hv), w2[i].x, s);
                s = fmaf(bf16hi(hv), w2[i].y, s);
            }
#pragma unroll
            for (int off = 16; off; off >>= 1) s += __shfl_xor_sync(0xffffffffu, s, off);
            if (lane == 0) ACT[r] = 1.f / (1.f + __expf(-(s + fca_b[0])));
        }
    }
    __syncthreads();

    // load vsT tile into BUF (256 v x 32 e bf16, u32 stride 17)
    for (int idx = t; idx < 256 * 16; idx += 512) {
        int n = idx >> 4, j = idx & 15;
        bufu[n * VST_U32_STRIDE + j] = ((const uint32_t*)g_vsTbf)[n * 16 + j];
    }
    __syncthreads();

    // ---- P4b: relation = emb @ vsT^T via HMMA (M=128,N=256,K=32) -----------
    {
        const int vg = ng;
#pragma unroll
        for (int nt = 0; nt < 16; nt++)
#pragma unroll
            for (int i = 0; i < 4; i++) d[nt][i] = 0.f;
#pragma unroll
        for (int ks = 0; ks < 2; ks++) {
            int aidx = (m0 + qrow) * EMB_U32_STRIDE + ks * 8 + qk;
            uint32_t a0 = embu[aidx];
            uint32_t a1 = embu[aidx + 8 * EMB_U32_STRIDE];
            uint32_t a2 = embu[aidx + 4];
            uint32_t a3 = embu[aidx + 8 * EMB_U32_STRIDE + 4];
#pragma unroll
            for (int nt = 0; nt < 16; nt++) {
                int n = vg * 128 + nt * 8 + qrow;
                int bidx = n * VST_U32_STRIDE + ks * 8 + qk;
                mma_bf16(d[nt][0], d[nt][1], d[nt][2], d[nt][3],
                         a0, a1, a2, a3, bufu[bidx], bufu[bidx + 4]);
            }
        }
        int rlo = m0 + qrow;
#pragma unroll
        for (int nt = 0; nt < 16; nt++) {
            int c0 = vg * 128 + nt * 8 + qk * 2;
            *(float2*)&H[rlo * 256 + c0]       = make_float2(d[nt][0], d[nt][1]);
            *(float2*)&H[(rlo + 8) * 256 + c0] = make_float2(d[nt][2], d[nt][3]);
        }
    }
    __syncthreads();

    // ---- softmax * act over H rows (warp = 8 rows) -------------------------
    for (int rr = 0; rr < 8; rr++) {
        int r = rbase + rr;
        float4 ra = *(float4*)&H[r * 256 + lane * 8];
        float4 rb = *(float4*)&H[r * 256 + lane * 8 + 4];
        float m = fmaxf(fmaxf(fmaxf(ra.x, ra.y), fmaxf(ra.z, ra.w)),
                        fmaxf(fmaxf(rb.x, rb.y), fmaxf(rb.z, rb.w)));
#pragma unroll
        for (int off = 16; off; off >>= 1)
            m = fmaxf(m, __shfl_xor_sync(0xffffffffu, m, off));
        ra.x = __expf(ra.x - m); ra.y = __expf(ra.y - m);
        ra.z = __expf(ra.z - m); ra.w = __expf(ra.w - m);
        rb.x = __expf(rb.x - m); rb.y = __expf(rb.y - m);
        rb.z = __expf(rb.z - m); rb.w = __expf(rb.w - m);
        float s = ra.x + ra.y + ra.z + ra.w + rb.x + rb.y + rb.z + rb.w;
#pragma unroll
        for (int off = 16; off; off >>= 1) s += __shfl_xor_sync(0xffffffffu, s, off);
        float sc = ACT[r] / s;
        ra.x *= sc; ra.y *= sc; ra.z *= sc; ra.w *= sc;
        rb.x *= sc; rb.y *= sc; rb.z *= sc; rb.w *= sc;
        *(float4*)&H[r * 256 + lane * 8]     = ra;
        *(float4*)&H[r * 256 + lane * 8 + 4] = rb;
    }
    __syncthreads();

    // ---- P5: out[b,:,n0:n0+128] = view_cell[b] @ route^T -------------------
    // split-bf16 HMMA: acc = Ahi*Bhi + Ahi*Blo + Alo*Bhi (fp32 accum)
    const int wm = wid >> 2, wn = wid & 3;
    float p5d[2][4][4];
#pragma unroll
    for (int mt = 0; mt < 2; mt++)
#pragma unroll
        for (int ntl = 0; ntl < 4; ntl++)
#pragma unroll
            for (int i = 0; i < 4; i++) p5d[mt][ntl][i] = 0.f;

    for (int vc = 0; vc < 4; vc++) {          // v-chunk of 64
        const int v0 = vc * 64;
        __syncthreads();
        {   // stage A hi/lo from global ([b][c][256] bf16; chunk = 32 u32/row)
            const uint4* sh = (const uint4*)((const uint32_t*)g_vchi + b * 16384 + (v0 >> 1));
            const uint4* sl = (const uint4*)((const uint32_t*)g_vclo + b * 16384 + (v0 >> 1));
            for (int i = t; i < 1024; i += 512) {
                int c = i >> 3, j = i & 7;
                *(uint4*)&AH[c * P5_STRIDE + j * 4] = sh[c * 32 + j];
                *(uint4*)&AL[c * P5_STRIDE + j * 4] = sl[c * 32 + j];
            }
        }
        {   // convert route chunk fp32 -> hi/lo bf16 (128 n-rows x 64 v)
            int n = t >> 2, seg = t & 3;
            const float* src = H + n * 256 + v0 + seg * 16;
            uint32_t* dh = BH + n * P5_STRIDE + seg * 8;
            uint32_t* dl = BL + n * P5_STRIDE + seg * 8;
#pragma unroll
            for (int j = 0; j < 8; j++) {
                float f0 = src[2 * j], f1 = src[2 * j + 1];
                uint32_t h = pack_bf16(f0, f1);
                dh[j] = h;
                dl[j] = pack_bf16(f0 - bf16lo(h), f1 - bf16hi(h));
            }
        }
        __syncthreads();
#pragma unroll
        for (int ks = 0; ks < 4; ks++) {
            uint32_t ah[2][4], al[2][4];
#pragma unroll
            for (int mt = 0; mt < 2; mt++) {
                int row = wm * 32 + mt * 16 + qrow;
                int aidx = row * P5_STRIDE + ks * 8 + qk;
                ah[mt][0] = AH[aidx];
                ah[mt][1] = AH[aidx + 8 * P5_STRIDE];
                ah[mt][2] = AH[aidx + 4];
                ah[mt][3] = AH[aidx + 8 * P5_STRIDE + 4];
                al[mt][0] = AL[aidx];
                al[mt][1] = AL[aidx + 8 * P5_STRIDE];
                al[mt][2] = AL[aidx + 4];
                al[mt][3] = AL[aidx + 8 * P5_STRIDE + 4];
            }
#pragma unroll
            for (int ntl = 0; ntl < 4; ntl++) {
                int n = wn * 32 + ntl * 8 + qrow;
                int bidx = n * P5_STRIDE + ks * 8 + qk;
                uint32_t bh0 = BH[bidx], bh1 = BH[bidx + 4];
                uint32_t bl0 = BL[bidx], bl1 = BL[bidx + 4];
#pragma unroll
                for (int mt = 0; mt < 2; mt++) {
                    mma_bf16(p5d[mt][ntl][0], p5d[mt][ntl][1], p5d[mt][ntl][2], p5d[mt][ntl][3],
                             ah[mt][0], ah[mt][1], ah[mt][2], ah[mt][3], bh0, bh1);
                    mma_bf16(p5d[mt][ntl][0], p5d[mt][ntl][1], p5d[mt][ntl][2], p5d[mt][ntl][3],
                             ah[mt][0], ah[mt][1], ah[mt][2], ah[mt][3], bl0, bl1);
                    mma_bf16(p5d[mt][ntl][0], p5d[mt][ntl][1], p5d[mt][ntl][2], p5d[mt][ntl][3],
                             al[mt][0], al[mt][1], al[mt][2], al[mt][3], bh0, bh1);
                }
            }
        }
    }

    // direct predicated stores: out[b][c][n], n contiguous
    float* outb = out + (size_t)b * kC * kN;
#pragma unroll
    for (int mt = 0; mt < 2; mt++) {
        int row = wm * 32 + mt * 16 + qrow;
        float* o0 = outb + (size_t)row * kN;
        float* o1 = o0 + 8 * kN;
#pragma unroll
        for (int ntl = 0; ntl < 4; ntl++) {
            int col = n0 + wn * 32 + ntl * 8 + qk * 2;
            if (col < kN) {
                *(float2*)&o0[col] = make_float2(p5d[mt][ntl][0], p5d[mt][ntl][1]);
                *(float2*)&o1[col] = make_float2(p5d[mt][ntl][2], p5d[mt][ntl][3]);
            }
        }
    }
}

// ---------------------------------------------------------------------------
extern "C" void kernel_launch(void* const* d_in, const int* in_sizes, int n_in,
                              void* d_out, int out_size) {
    const float* view_cell = (const float*)d_in[0];
    const float* v         = (const float*)d_in[1];
    const float* w2c_w1    = (const float*)d_in[2];
    const float* w2c_b1    = (const float*)d_in[3];
    const float* w2c_w2    = (const float*)d_in[4];
    const float* w2c_b2    = (const float*)d_in[5];
    const float* fc1_w     = (const float*)d_in[6];
    const float* fc1_b     = (const float*)d_in[7];
    const float* fc2_w     = (const float*)d_in[8];
    const float* fc2_b     = (const float*)d_in[9];
    const float* fca_w     = (const float*)d_in[10];
    const float* fca_b     = (const float*)d_in[11];
    const float* fce_w     = (const float*)d_in[12];
    const float* fce_b     = (const float*)d_in[13];
    const float* vse_w1    = (const float*)d_in[14];
    const float* vse_b1    = (const float*)d_in[15];
    const float* vse_w2    = (const float*)d_in[16];
    const float* vse_b2    = (const float*)d_in[17];
    float* out = (float*)d_out;

    cudaFuncSetAttribute(mega_kernel, cudaFuncAttributeMaxDynamicSharedMemorySize,
                         SM_BYTES);

    prep_kernel<<<2420, 512>>>(v, w2c_w1, w2c_b1, w2c_b2,
                               vse_w1, vse_b1, vse_w2, vse_b2,
                               fc2_w, fce_w, view_cell);

    dim3 wgrid(47, 8);
    wcode_kernel<<<wgrid, 128>>>(w2c_w2);

    dim3 grid((kN + TR - 1) / TR, kB);  // (16, 64)
    mega_kernel<<<grid, 512, SM_BYTES>>>(fc1_w, fc1_b, fc2_b,
                                         fca_w, fca_b, fce_b,
                                         out);
}